// round 8
// baseline (speedup 1.0000x reference)
#include <cuda_runtime.h>
#include <cuda_bf16.h>
#include <math.h>

// ---------------------------------------------------------------------------
// TransformerEncoderBlock: B=4, S=2048, D=1024, H=16, Dk=64, Dff=4096, fp32.
// Round 8: R4 GEMM structure exactly, single change BK 16->32 (half the
// barrier count, double compute per sync). Launches reordered so ncu's
// "-s 5 -c 1" captures the QKV GEMM. Attention: R4 mma flash (unchanged).
// ---------------------------------------------------------------------------

#define BATCH   4
#define SEQ     2048
#define DMODEL  1024
#define NHEADS  16
#define DK      64
#define DFF     4096
#define MROWS   (BATCH * SEQ)   // 8192

#define LROW    40              // padded row: 32 + 8 bf16 (conflict-free)

// ---------------- scratch (__device__ globals; no allocs allowed) ----------
__device__ float g_x1[MROWS * DMODEL];

__device__ __align__(16) __nv_bfloat16 g_hh  [MROWS * DMODEL];
__device__ __align__(16) __nv_bfloat16 g_hl  [MROWS * DMODEL];
__device__ __align__(16) __nv_bfloat16 g_qh  [MROWS * DMODEL];
__device__ __align__(16) __nv_bfloat16 g_ql  [MROWS * DMODEL];
__device__ __align__(16) __nv_bfloat16 g_kh  [MROWS * DMODEL];
__device__ __align__(16) __nv_bfloat16 g_kl  [MROWS * DMODEL];
__device__ __align__(16) __nv_bfloat16 g_vh  [MROWS * DMODEL];
__device__ __align__(16) __nv_bfloat16 g_vl  [MROWS * DMODEL];
__device__ __align__(16) __nv_bfloat16 g_ctxh[MROWS * DMODEL];
__device__ __align__(16) __nv_bfloat16 g_ctxl[MROWS * DMODEL];
__device__ __align__(16) __nv_bfloat16 g_h2h [MROWS * DMODEL];
__device__ __align__(16) __nv_bfloat16 g_h2l [MROWS * DMODEL];
__device__ __align__(16) __nv_bfloat16 g_ffnh[MROWS * DFF];
__device__ __align__(16) __nv_bfloat16 g_ffnl[MROWS * DFF];

__device__ __align__(16) __nv_bfloat16 g_wqh[DMODEL*DMODEL], g_wql[DMODEL*DMODEL];
__device__ __align__(16) __nv_bfloat16 g_wkh[DMODEL*DMODEL], g_wkl[DMODEL*DMODEL];
__device__ __align__(16) __nv_bfloat16 g_wvh[DMODEL*DMODEL], g_wvl[DMODEL*DMODEL];
__device__ __align__(16) __nv_bfloat16 g_woh[DMODEL*DMODEL], g_wol[DMODEL*DMODEL];
__device__ __align__(16) __nv_bfloat16 g_w1h[DFF*DMODEL],    g_w1l[DFF*DMODEL];
__device__ __align__(16) __nv_bfloat16 g_w2h[DMODEL*DFF],    g_w2l[DMODEL*DFF];

// ---------------------------------------------------------------------------
__device__ __forceinline__ void split_bf16(float v, __nv_bfloat16& hi, __nv_bfloat16& lo) {
    hi = __float2bfloat16(v);
    lo = __float2bfloat16(v - __bfloat162float(hi));
}
__device__ __forceinline__ float gelu_exact(float x) {
    return 0.5f * x * (1.0f + erff(x * 0.70710678118654752f));
}
__device__ __forceinline__ void cp16(const void* dst_smem, const void* src) {
    unsigned s = (unsigned)__cvta_generic_to_shared(dst_smem);
    asm volatile("cp.async.cg.shared.global [%0], [%1], 16;\n" :: "r"(s), "l"(src));
}
__device__ __forceinline__ void cp16u(unsigned dst_smem, const void* src) {
    asm volatile("cp.async.cg.shared.global [%0], [%1], 16;\n" :: "r"(dst_smem), "l"(src));
}
__device__ __forceinline__ void mma_bf16(float* c, const unsigned* a, const unsigned* b) {
    asm volatile(
        "mma.sync.aligned.m16n8k16.row.col.f32.bf16.bf16.f32 "
        "{%0,%1,%2,%3}, {%4,%5,%6,%7}, {%8,%9}, {%0,%1,%2,%3};\n"
        : "+f"(c[0]), "+f"(c[1]), "+f"(c[2]), "+f"(c[3])
        : "r"(a[0]), "r"(a[1]), "r"(a[2]), "r"(a[3]), "r"(b[0]), "r"(b[1]));
}
__device__ __forceinline__ void ldsm4(unsigned& r0, unsigned& r1, unsigned& r2, unsigned& r3, unsigned addr) {
    asm volatile("ldmatrix.sync.aligned.m8n8.x4.shared.b16 {%0,%1,%2,%3}, [%4];"
                 : "=r"(r0), "=r"(r1), "=r"(r2), "=r"(r3) : "r"(addr));
}
__device__ __forceinline__ void ldsm4t(unsigned& r0, unsigned& r1, unsigned& r2, unsigned& r3, unsigned addr) {
    asm volatile("ldmatrix.sync.aligned.m8n8.x4.trans.shared.b16 {%0,%1,%2,%3}, [%4];"
                 : "=r"(r0), "=r"(r1), "=r"(r2), "=r"(r3) : "r"(addr));
}
// FFMA-only e^x for x <= 0 (clamped). rel err ~4e-5.
__device__ __forceinline__ float fexp(float x) {
    x = fmaxf(x, -60.0f);
    float t = x * 1.4426950408889634f;
    float z = t + 12582912.0f;
    int   e = __float_as_int(z) - 0x4B400000;
    float f = t - (z - 12582912.0f);
    float p = 0.0096181291f;
    p = fmaf(p, f, 0.0555041087f);
    p = fmaf(p, f, 0.2402265070f);
    p = fmaf(p, f, 0.6931471806f);
    p = fmaf(p, f, 1.0f);
    return __int_as_float(__float_as_int(p) + (e << 23));
}
__device__ __forceinline__ void pack_hilo(float a, float b, unsigned& hi, unsigned& lo) {
    __nv_bfloat162 h2 = __float22bfloat162_rn(make_float2(a, b));
    float2 hf = __bfloat1622float2(h2);
    __nv_bfloat162 l2 = __float22bfloat162_rn(make_float2(a - hf.x, b - hf.y));
    hi = *(unsigned*)&h2;
    lo = *(unsigned*)&l2;
}

// ---------------------------------------------------------------------------
// Weight split + transpose:  W[K][N] fp32  ->  Th/Tl[N][K] bf16
// ---------------------------------------------------------------------------
__global__ __launch_bounds__(256) void wsplit_kernel(
    const float* __restrict__ W, __nv_bfloat16* __restrict__ Th,
    __nv_bfloat16* __restrict__ Tl, int K, int N)
{
    __shared__ float tile[32][33];
    int n0 = blockIdx.x * 32, k0 = blockIdx.y * 32;
    int tx = threadIdx.x & 31;
    int ty = threadIdx.x >> 5;
    #pragma unroll
    for (int i = 0; i < 32; i += 8)
        tile[ty + i][tx] = W[(size_t)(k0 + ty + i) * N + n0 + tx];
    __syncthreads();
    #pragma unroll
    for (int i = 0; i < 32; i += 8) {
        float v = tile[tx][ty + i];
        __nv_bfloat16 hi, lo; split_bf16(v, hi, lo);
        size_t o = (size_t)(n0 + ty + i) * K + k0 + tx;
        Th[o] = hi; Tl[o] = lo;
    }
}

// ---------------------------------------------------------------------------
// LayerNorm -> bf16 hi/lo outputs.
// ---------------------------------------------------------------------------
__global__ __launch_bounds__(256) void ln_kernel(
    const float* __restrict__ x, const float* __restrict__ gamma,
    const float* __restrict__ beta,
    __nv_bfloat16* __restrict__ out_hi, __nv_bfloat16* __restrict__ out_lo)
{
    int row = blockIdx.x;
    int tid = threadIdx.x;
    const float4* xr = (const float4*)(x + (size_t)row * DMODEL);
    float4 v = xr[tid];

    __shared__ float red[256];
    red[tid] = v.x + v.y + v.z + v.w; __syncthreads();
    #pragma unroll
    for (int off = 128; off > 0; off >>= 1) {
        if (tid < off) red[tid] += red[tid + off];
        __syncthreads();
    }
    float mu = red[0] * (1.0f / DMODEL);
    __syncthreads();

    float dx0 = v.x - mu, dx1 = v.y - mu, dx2 = v.z - mu, dx3 = v.w - mu;
    red[tid] = dx0*dx0 + dx1*dx1 + dx2*dx2 + dx3*dx3; __syncthreads();
    #pragma unroll
    for (int off = 128; off > 0; off >>= 1) {
        if (tid < off) red[tid] += red[tid + off];
        __syncthreads();
    }
    float rs = rsqrtf(red[0] * (1.0f / DMODEL) + 1e-5f);

    float4 g4 = ((const float4*)gamma)[tid];
    float4 b4 = ((const float4*)beta)[tid];
    float o0 = dx0 * rs * g4.x + b4.x;
    float o1 = dx1 * rs * g4.y + b4.y;
    float o2 = dx2 * rs * g4.z + b4.z;
    float o3 = dx3 * rs * g4.w + b4.w;

    unsigned h01, l01, h23, l23;
    pack_hilo(o0, o1, h01, l01);
    pack_hilo(o2, o3, h23, l23);
    size_t o = (size_t)row * DMODEL + tid * 4;
    *(unsigned*)&out_hi[o]   = h01; *(unsigned*)&out_hi[o+2] = h23;
    *(unsigned*)&out_lo[o]   = l01; *(unsigned*)&out_lo[o+2] = l23;
}

// ---------------------------------------------------------------------------
// bf16x3 MMA GEMM (R4 structure, BK=32): C = (Ah+Al) @ (Bh+Bl)^T + bias ...
// CTA 128x128, 256 threads (8 warps 2x4), warp tile 64x32.
// k-tile 32 (2 sub-steps of 16); rows padded to 40 bf16 -> conflict-free.
// Dynamic smem: 2 stages x 4 matrices x 128x40 bf16 = 81920 B.
// EPI: 1 bias+R->f32 | 2 bias+gelu->bf16 hi/lo | 3 bias->bf16 hi/lo
// ---------------------------------------------------------------------------
#define GM_MAT   (128 * LROW * 2)     // 10240 bytes per matrix tile
#define GM_STG   (4 * GM_MAT)         // 40960 bytes per stage
#define GM_SMEM  (2 * GM_STG)         // 81920 bytes

template<int EPI>
__global__ __launch_bounds__(256) void mma_gemm(
    const __nv_bfloat16* __restrict__ Ah, const __nv_bfloat16* __restrict__ Al,
    const __nv_bfloat16* __restrict__ Bh, const __nv_bfloat16* __restrict__ Bl,
    const float* __restrict__ bias, const float* __restrict__ R,
    float* __restrict__ C, __nv_bfloat16* __restrict__ Chi,
    __nv_bfloat16* __restrict__ Clo, int M, int N, int K)
{
    extern __shared__ __align__(16) char smg[];
    const unsigned smb = (unsigned)__cvta_generic_to_shared(smg);

    const int tid = threadIdx.x;
    const int bm = blockIdx.y * 128;
    const int bn = blockIdx.x * 128;

    const int warp  = tid >> 5;
    const int lane  = tid & 31;
    const int warpm = warp >> 2;
    const int warpn = warp & 3;
    const int g = lane >> 2;
    const int c = lane & 3;

    float acc[4][4][4];
    #pragma unroll
    for (int i = 0; i < 4; i++)
        #pragma unroll
        for (int j = 0; j < 4; j++)
            #pragma unroll
            for (int r = 0; r < 4; r++) acc[i][j][r] = 0.0f;

    // stage loader: per matrix 128 rows x 4 chunks of 16B; 2 chunks/thread
    auto load_stage = [&](int s, int kt) {
        const unsigned sb = smb + s * GM_STG;
        const int k0 = kt * 32;
        #pragma unroll
        for (int j = 0; j < 2; j++) {
            int idx = tid + j * 256;
            int row = idx >> 2, q = idx & 3;
            unsigned d = (unsigned)(row * LROW + q * 8) * 2;
            size_t ga = (size_t)(bm + row) * K + k0 + q * 8;
            size_t gb = (size_t)(bn + row) * K + k0 + q * 8;
            cp16u(sb + d,              Ah + ga);
            cp16u(sb + GM_MAT + d,     Al + ga);
            cp16u(sb + 2 * GM_MAT + d, Bh + gb);
            cp16u(sb + 3 * GM_MAT + d, Bl + gb);
        }
        asm volatile("cp.async.commit_group;\n" ::);
    };

    const int nk = K >> 5;
    load_stage(0, 0);

    for (int t = 0; t < nk; t++) {
        asm volatile("cp.async.wait_group 0;\n" ::);
        __syncthreads();
        if (t + 1 < nk) load_stage((t + 1) & 1, t + 1);

        const __nv_bfloat16* sAh = (const __nv_bfloat16*)(smg + (t & 1) * GM_STG);
        const __nv_bfloat16* sAl = (const __nv_bfloat16*)(smg + (t & 1) * GM_STG + GM_MAT);
        const __nv_bfloat16* sBh = (const __nv_bfloat16*)(smg + (t & 1) * GM_STG + 2 * GM_MAT);
        const __nv_bfloat16* sBl = (const __nv_bfloat16*)(smg + (t & 1) * GM_STG + 3 * GM_MAT);

        #pragma unroll
        for (int ks = 0; ks < 2; ks++) {
            const int kofs = ks * 16;
            unsigned ah[4][4], al[4][4], bh[4][2], bl[4][2];
            const int abase = (warpm * 64 + g) * LROW + c * 2 + kofs;
            const int bbase = (warpn * 32 + g) * LROW + c * 2 + kofs;

            #pragma unroll
            for (int mi = 0; mi < 4; mi++) {
                int o = abase + mi * 16 * LROW;
                ah[mi][0] = *(const unsigned*)(sAh + o);
                ah[mi][1] = *(const unsigned*)(sAh + o + 8 * LROW);
                ah[mi][2] = *(const unsigned*)(sAh + o + 8);
                ah[mi][3] = *(const unsigned*)(sAh + o + 8 * LROW + 8);
            }
            #pragma unroll
            for (int ni = 0; ni < 4; ni++) {
                int o = bbase + ni * 8 * LROW;
                bh[ni][0] = *(const unsigned*)(sBh + o);
                bh[ni][1] = *(const unsigned*)(sBh + o + 8);
            }
            #pragma unroll
            for (int mi = 0; mi < 4; mi++)
                #pragma unroll
                for (int ni = 0; ni < 4; ni++)
                    mma_bf16(acc[mi][ni], ah[mi], bh[ni]);
            #pragma unroll
            for (int mi = 0; mi < 4; mi++) {
                int o = abase + mi * 16 * LROW;
                al[mi][0] = *(const unsigned*)(sAl + o);
                al[mi][1] = *(const unsigned*)(sAl + o + 8 * LROW);
                al[mi][2] = *(const unsigned*)(sAl + o + 8);
                al[mi][3] = *(const unsigned*)(sAl + o + 8 * LROW + 8);
            }
            #pragma unroll
            for (int mi = 0; mi < 4; mi++)
                #pragma unroll
                for (int ni = 0; ni < 4; ni++)
                    mma_bf16(acc[mi][ni], al[mi], bh[ni]);
            #pragma unroll
            for (int ni = 0; ni < 4; ni++) {
                int o = bbase + ni * 8 * LROW;
                bl[ni][0] = *(const unsigned*)(sBl + o);
                bl[ni][1] = *(const unsigned*)(sBl + o + 8);
            }
            #pragma unroll
            for (int mi = 0; mi < 4; mi++)
                #pragma unroll
                for (int ni = 0; ni < 4; ni++)
                    mma_bf16(acc[mi][ni], ah[mi], bl[ni]);
        }
    }

    // epilogue (R4)
    #pragma unroll
    for (int mi = 0; mi < 4; mi++) {
        int r0 = bm + warpm * 64 + mi * 16 + g;
        #pragma unroll
        for (int ni = 0; ni < 4; ni++) {
            int col = bn + warpn * 32 + ni * 8 + c * 2;
            float2 bia = *(const float2*)&bias[col];
            float v0 = acc[mi][ni][0] + bia.x;
            float v1 = acc[mi][ni][1] + bia.y;
            float v2 = acc[mi][ni][2] + bia.x;
            float v3 = acc[mi][ni][3] + bia.y;
            size_t o0 = (size_t)r0 * N + col;
            size_t o1 = (size_t)(r0 + 8) * N + col;
            if (EPI == 1) {
                float2 ra = *(const float2*)&R[o0];
                float2 rb = *(const float2*)&R[o1];
                v0 += ra.x; v1 += ra.y; v2 += rb.x; v3 += rb.y;
                *(float2*)&C[o0] = make_float2(v0, v1);
                *(float2*)&C[o1] = make_float2(v2, v3);
            } else {
                if (EPI == 2) {
                    v0 = gelu_exact(v0); v1 = gelu_exact(v1);
                    v2 = gelu_exact(v2); v3 = gelu_exact(v3);
                }
                unsigned h01, l01, h23, l23;
                pack_hilo(v0, v1, h01, l01);
                pack_hilo(v2, v3, h23, l23);
                *(unsigned*)&Chi[o0] = h01; *(unsigned*)&Chi[o1] = h23;
                *(unsigned*)&Clo[o0] = l01; *(unsigned*)&Clo[o1] = l23;
            }
        }
    }
}

// ---------------------------------------------------------------------------
// Tensor-core flash attention (R4, unchanged).
// ---------------------------------------------------------------------------
#define ATT_QH   0
#define ATT_QL   8192
#define ATT_KH   16384
#define ATT_TILE 8192
#define ATT_FM   (16384 + 2*32768)
#define ATT_SMEM (ATT_FM + 2*64*4)

__device__ __forceinline__ unsigned swz(unsigned base, int row, int cc) {
    return base + (unsigned)((row << 7) + (((cc ^ row) & 7) << 4));
}

__global__ __launch_bounds__(128) void attn_mma(
    const __nv_bfloat16* __restrict__ Qh, const __nv_bfloat16* __restrict__ Ql,
    const __nv_bfloat16* __restrict__ Kh, const __nv_bfloat16* __restrict__ Kl,
    const __nv_bfloat16* __restrict__ Vh, const __nv_bfloat16* __restrict__ Vl,
    const int* __restrict__ mask,
    __nv_bfloat16* __restrict__ Ohi, __nv_bfloat16* __restrict__ Olo)
{
    extern __shared__ __align__(16) char sm[];
    const unsigned smb = (unsigned)__cvta_generic_to_shared(sm);
    float* fmask = (float*)(sm + ATT_FM);

    const int b  = blockIdx.z;
    const int h  = blockIdx.y;
    const int qt = blockIdx.x;
    const int tid  = threadIdx.x;
    const int warp = tid >> 5;
    const int lane = tid & 31;
    const int li  = lane & 7;
    const int grp = lane >> 3;
    const int g = lane >> 2;
    const int c = lane & 3;

    const int qrow0 = qt * 64;
    const size_t rowQ = (size_t)(b * SEQ + qrow0);

    {
        #pragma unroll
        for (int i = 0; i < 4; i++) {
            int idx = tid + i * 128;
            int row = idx >> 3, cc = idx & 7;
            const __nv_bfloat16* sq = Qh + (rowQ + row) * DMODEL + h * DK + cc * 8;
            const __nv_bfloat16* sq2 = Ql + (rowQ + row) * DMODEL + h * DK + cc * 8;
            cp16(sm + swz(ATT_QH, row, cc), sq);
            cp16(sm + swz(ATT_QL, row, cc), sq2);
        }
        #pragma unroll
        for (int i = 0; i < 4; i++) {
            int idx = tid + i * 128;
            int row = idx >> 3, cc = idx & 7;
            size_t gr = (size_t)(b * SEQ + row) * DMODEL + h * DK + cc * 8;
            cp16(sm + swz(ATT_KH, row, cc), Kh + gr);
            cp16(sm + swz(ATT_KH + ATT_TILE, row, cc), Kl + gr);
            cp16(sm + swz(ATT_KH + 2*ATT_TILE, row, cc), Vh + gr);
            cp16(sm + swz(ATT_KH + 3*ATT_TILE, row, cc), Vl + gr);
        }
        if (tid < 64) fmask[tid] = (mask[b * SEQ + tid] != 0) ? 0.0f : -1e30f;
        asm volatile("cp.async.commit_group;\n" ::);
    }

    float oacc[8][4];
    #pragma unroll
    for (int nt = 0; nt < 8; nt++)
        #pragma unroll
        for (int r = 0; r < 4; r++) oacc[nt][r] = 0.0f;
    float m0 = -1e30f, m1 = -1e30f, l0 = 0.0f, l1 = 0.0f;
    unsigned qfh[4][4], qfl[4][4];

    const int NT = SEQ / 64;
    for (int kt = 0; kt < NT; kt++) {
        asm volatile("cp.async.wait_group 0;\n" ::);
        __syncthreads();

        if (kt == 0) {
            int qrow = warp * 16 + ((grp & 1) << 3) + li;
            #pragma unroll
            for (int q = 0; q < 4; q++) {
                int cc = 2 * q + (grp >> 1);
                ldsm4(qfh[q][0], qfh[q][1], qfh[q][2], qfh[q][3], smb + swz(ATT_QH, qrow, cc));
                ldsm4(qfl[q][0], qfl[q][1], qfl[q][2], qfl[q][3], smb + swz(ATT_QL, qrow, cc));
            }
        }

        if (kt + 1 < NT) {
            int s = (kt + 1) & 1;
            int kb = (kt + 1) * 64;
            #pragma unroll
            for (int i = 0; i < 4; i++) {
                int idx = tid + i * 128;
                int row = idx >> 3, cc = idx & 7;
                size_t gr = (size_t)(b * SEQ + kb + row) * DMODEL + h * DK + cc * 8;
                cp16(sm + swz(ATT_KH + s*32768, row, cc), Kh + gr);
                cp16(sm + swz(ATT_KH + s*32768 + ATT_TILE, row, cc), Kl + gr);
                cp16(sm + swz(ATT_KH + s*32768 + 2*ATT_TILE, row, cc), Vh + gr);
                cp16(sm + swz(ATT_KH + s*32768 + 3*ATT_TILE, row, cc), Vl + gr);
            }
            if (tid < 64) fmask[s * 64 + tid] = (mask[b * SEQ + kb + tid] != 0) ? 0.0f : -1e30f;
            asm volatile("cp.async.commit_group;\n" ::);
        }

        const int s = kt & 1;
        const unsigned KHb = ATT_KH + s*32768;
        const unsigned KLb = KHb + ATT_TILE;
        const unsigned VHb = KHb + 2*ATT_TILE;
        const unsigned VLb = KHb + 3*ATT_TILE;
        const float* fm = fmask + s * 64;

        float sacc[8][4];
        #pragma unroll
        for (int nt = 0; nt < 8; nt++)
            #pragma unroll
            for (int r = 0; r < 4; r++) sacc[nt][r] = 0.0f;

        {
            const int krow = ((grp >> 1) << 3) + li;
            const int kccb = grp & 1;
            #pragma unroll
            for (int q = 0; q < 4; q++) {
                unsigned kb2[8][2];
                #pragma unroll
                for (int p = 0; p < 4; p++)
                    ldsm4(kb2[2*p][0], kb2[2*p][1], kb2[2*p+1][0], kb2[2*p+1][1],
                          smb + swz(KHb, 16*p + krow, 2*q + kccb));
                #pragma unroll
                for (int nt = 0; nt < 8; nt++) mma_bf16(sacc[nt], qfh[q], kb2[nt]);
                #pragma unroll
                for (int nt = 0; nt < 8; nt++) mma_bf16(sacc[nt], qfl[q], kb2[nt]);
                #pragma unroll
                for (int p = 0; p < 4; p++)
                    ldsm4(kb2[2*p][0], kb2[2*p][1], kb2[2*p+1][0], kb2[2*p+1][1],
                          smb + swz(KLb, 16*p + krow, 2*q + kccb));
                #pragma unroll
                for (int nt = 0; nt < 8; nt++) mma_bf16(sacc[nt], qfh[q], kb2[nt]);
            }
        }

        float mx0 = -1e30f, mx1 = -1e30f;
        #pragma unroll
        for (int nt = 0; nt < 8; nt++) {
            float f0 = fm[nt*8 + 2*c];
            float f1 = fm[nt*8 + 2*c + 1];
            sacc[nt][0] = fmaf(sacc[nt][0], 0.125f, f0);
            sacc[nt][1] = fmaf(sacc[nt][1], 0.125f, f1);
            sacc[nt][2] = fmaf(sacc[nt][2], 0.125f, f0);
            sacc[nt][3] = fmaf(sacc[nt][3], 0.125f, f1);
            mx0 = fmaxf(mx0, fmaxf(sacc[nt][0], sacc[nt][1]));
            mx1 = fmaxf(mx1, fmaxf(sacc[nt][2], sacc[nt][3]));
        }
        mx0 = fmaxf(mx0, __shfl_xor_sync(0xffffffff, mx0, 1));
        mx0 = fmaxf(mx0, __shfl_xor_sync(0xffffffff, mx0, 2));
        mx1 = fmaxf(mx1, __shfl_xor_sync(0xffffffff, mx1, 1));
        mx1 = fmaxf(mx1, __shfl_xor_sync(0xffffffff, mx1, 2));

        float nm0 = fmaxf(m0, mx0), nm1 = fmaxf(m1, mx1);
        float sc0 = fexp(m0 - nm0), sc1 = fexp(m1 - nm1);
        m0 = nm0; m1 = nm1;
        l0 *= sc0; l1 *= sc1;
        #pragma unroll
        for (int nt = 0; nt < 8; nt++) {
            oacc[nt][0] *= sc0; oacc[nt][1] *= sc0;
            oacc[nt][2] *= sc1; oacc[nt][3] *= sc1;
        }

        float ls0 = 0.0f, ls1 = 0.0f;
        #pragma unroll
        for (int nt = 0; nt < 8; nt++) {
            float p0 = fexp(sacc[nt][0] - nm0);
            float p1 = fexp(sacc[nt][1] - nm0);
            float p2 = fexp(sacc[nt][2] - nm1);
            float p3 = fexp(sacc[nt][3] - nm1);
            sacc[nt][0] = p0; sacc[nt][1] = p1; sacc[nt][2] = p2; sacc[nt][3] = p3;
            ls0 += p0 + p1; ls1 += p2 + p3;
        }
        ls0 += __shfl_xor_sync(0xffffffff, ls0, 1);
        ls0 += __shfl_xor_sync(0xffffffff, ls0, 2);
        ls1 += __shfl_xor_sync(0xffffffff, ls1, 1);
        ls1 += __shfl_xor_sync(0xffffffff, ls1, 2);
        l0 += ls0; l1 += ls1;

        unsigned pfh[4][4], pfl[4][4];
        #pragma unroll
        for (int j = 0; j < 4; j++) {
            pack_hilo(sacc[2*j][0],   sacc[2*j][1],   pfh[j][0], pfl[j][0]);
            pack_hilo(sacc[2*j][2],   sacc[2*j][3],   pfh[j][1], pfl[j][1]);
            pack_hilo(sacc[2*j+1][0], sacc[2*j+1][1], pfh[j][2], pfl[j][2]);
            pack_hilo(sacc[2*j+1][2], sacc[2*j+1][3], pfh[j][3], pfl[j][3]);
        }

        {
            const int vrow = ((grp & 1) << 3) + li;
            const int vccb = grp >> 1;
            #pragma unroll
            for (int j = 0; j < 4; j++) {
                unsigned vb2[8][2];
                #pragma unroll
                for (int d = 0; d < 8; d += 2)
                    ldsm4t(vb2[d][0], vb2[d][1], vb2[d+1][0], vb2[d+1][1],
                           smb + swz(VHb, 16*j + vrow, d + vccb));
                #pragma unroll
                for (int nt = 0; nt < 8; nt++) mma_bf16(oacc[nt], pfh[j], vb2[nt]);
                #pragma unroll
                for (int nt = 0; nt < 8; nt++) mma_bf16(oacc[nt], pfl[j], vb2[nt]);
                #pragma unroll
                for (int d = 0; d < 8; d += 2)
                    ldsm4t(vb2[d][0], vb2[d][1], vb2[d+1][0], vb2[d+1][1],
                           smb + swz(VLb, 16*j + vrow, d + vccb));
                #pragma unroll
                for (int nt = 0; nt < 8; nt++) mma_bf16(oacc[nt], pfh[j], vb2[nt]);
            }
        }
    }

    float inv0 = 1.0f / l0, inv1 = 1.0f / l1;
    int r0 = qrow0 + warp * 16 + g;
    int r1 = r0 + 8;
    size_t base0 = (size_t)(b * SEQ + r0) * DMODEL + h * DK;
    size_t base1 = (size_t)(b * SEQ + r1) * DMODEL + h * DK;
    #pragma unroll
    for (int nt = 0; nt < 8; nt++) {
        int col = nt * 8 + 2 * c;
        unsigned hi0, lo0, hi1, lo1;
        pack_hilo(oacc[nt][0] * inv0, oacc[nt][1] * inv0, hi0, lo0);
        pack_hilo(oacc[nt][2] * inv1, oacc[nt][3] * inv1, hi1, lo1);
        *(unsigned*)&Ohi[base0 + col] = hi0;
        *(unsigned*)&Olo[base0 + col] = lo0;
        *(unsigned*)&Ohi[base1 + col] = hi1;
        *(unsigned*)&Olo[base1 + col] = lo1;
    }
}

// ---------------------------------------------------------------------------
// Host launch (ordered so ncu -s 5 -c 1 captures the QKV GEMM at index 5)
// ---------------------------------------------------------------------------
extern "C" void kernel_launch(void* const* d_in, const int* in_sizes, int n_in,
                              void* d_out, int out_size)
{
    const float* x     = (const float*)d_in[0];
    const int*   mask  = (const int*)  d_in[1];
    const float* Wq    = (const float*)d_in[2];
    const float* bq    = (const float*)d_in[3];
    const float* Wk    = (const float*)d_in[4];
    const float* bk    = (const float*)d_in[5];
    const float* Wv    = (const float*)d_in[6];
    const float* bv    = (const float*)d_in[7];
    const float* Wo    = (const float*)d_in[8];
    const float* bo    = (const float*)d_in[9];
    const float* W1    = (const float*)d_in[10];
    const float* b1    = (const float*)d_in[11];
    const float* W2    = (const float*)d_in[12];
    const float* b2    = (const float*)d_in[13];
    const float* ln1_g = (const float*)d_in[14];
    const float* ln1_b = (const float*)d_in[15];
    const float* ln2_g = (const float*)d_in[16];
    const float* ln2_b = (const float*)d_in[17];
    float* out = (float*)d_out;

    float* x1;
    __nv_bfloat16 *hh, *hl, *qh, *ql, *kh, *kl, *vh, *vl, *ctxh, *ctxl, *h2h, *h2l, *ffnh, *ffnl;
    __nv_bfloat16 *wqh,*wql,*wkh,*wkl,*wvh,*wvl,*woh,*wol,*w1h,*w1l,*w2h,*w2l;
    cudaGetSymbolAddress((void**)&x1,  g_x1);
    cudaGetSymbolAddress((void**)&hh,  g_hh);
    cudaGetSymbolAddress((void**)&hl,  g_hl);
    cudaGetSymbolAddress((void**)&qh,  g_qh);  cudaGetSymbolAddress((void**)&ql, g_ql);
    cudaGetSymbolAddress((void**)&kh,  g_kh);  cudaGetSymbolAddress((void**)&kl, g_kl);
    cudaGetSymbolAddress((void**)&vh,  g_vh);  cudaGetSymbolAddress((void**)&vl, g_vl);
    cudaGetSymbolAddress((void**)&ctxh, g_ctxh);
    cudaGetSymbolAddress((void**)&ctxl, g_ctxl);
    cudaGetSymbolAddress((void**)&h2h, g_h2h);
    cudaGetSymbolAddress((void**)&h2l, g_h2l);
    cudaGetSymbolAddress((void**)&ffnh, g_ffnh);
    cudaGetSymbolAddress((void**)&ffnl, g_ffnl);
    cudaGetSymbolAddress((void**)&wqh, g_wqh); cudaGetSymbolAddress((void**)&wql, g_wql);
    cudaGetSymbolAddress((void**)&wkh, g_wkh); cudaGetSymbolAddress((void**)&wkl, g_wkl);
    cudaGetSymbolAddress((void**)&wvh, g_wvh); cudaGetSymbolAddress((void**)&wvl, g_wvl);
    cudaGetSymbolAddress((void**)&woh, g_woh); cudaGetSymbolAddress((void**)&wol, g_wol);
    cudaGetSymbolAddress((void**)&w1h, g_w1h); cudaGetSymbolAddress((void**)&w1l, g_w1l);
    cudaGetSymbolAddress((void**)&w2h, g_w2h); cudaGetSymbolAddress((void**)&w2l, g_w2l);

    cudaFuncSetAttribute(attn_mma,    cudaFuncAttributeMaxDynamicSharedMemorySize, ATT_SMEM);
    cudaFuncSetAttribute(mma_gemm<1>, cudaFuncAttributeMaxDynamicSharedMemorySize, GM_SMEM);
    cudaFuncSetAttribute(mma_gemm<2>, cudaFuncAttributeMaxDynamicSharedMemorySize, GM_SMEM);
    cudaFuncSetAttribute(mma_gemm<3>, cudaFuncAttributeMaxDynamicSharedMemorySize, GM_SMEM);

    dim3 gW(DMODEL/32, DMODEL/32);
    dim3 gP(DMODEL/128, MROWS/128);

    // launches 0-3: QKVO weight splits
    wsplit_kernel<<<gW, 256>>>(Wq, wqh, wql, DMODEL, DMODEL);
    wsplit_kernel<<<gW, 256>>>(Wk, wkh, wkl, DMODEL, DMODEL);
    wsplit_kernel<<<gW, 256>>>(Wv, wvh, wvl, DMODEL, DMODEL);
    wsplit_kernel<<<gW, 256>>>(Wo, woh, wol, DMODEL, DMODEL);

    // launch 4: LN1
    ln_kernel<<<MROWS, 256>>>(x, ln1_g, ln1_b, hh, hl);

    // launch 5: Q projection  <-- ncu captures this one
    mma_gemm<3><<<gP, 256, GM_SMEM>>>(hh, hl, wqh, wql, bq, nullptr, nullptr, qh, ql, MROWS, DMODEL, DMODEL);
    mma_gemm<3><<<gP, 256, GM_SMEM>>>(hh, hl, wkh, wkl, bk, nullptr, nullptr, kh, kl, MROWS, DMODEL, DMODEL);
    mma_gemm<3><<<gP, 256, GM_SMEM>>>(hh, hl, wvh, wvl, bv, nullptr, nullptr, vh, vl, MROWS, DMODEL, DMODEL);

    // FFN weight splits (needed later)
    dim3 gW1(DFF/32, DMODEL/32);
    wsplit_kernel<<<gW1, 256>>>(W1, w1h, w1l, DMODEL, DFF);
    dim3 gW2(DMODEL/32, DFF/32);
    wsplit_kernel<<<gW2, 256>>>(W2, w2h, w2l, DFF, DMODEL);

    // attention -> ctx bf16 hi/lo
    dim3 gA(SEQ/64, NHEADS, BATCH);
    attn_mma<<<gA, 128, ATT_SMEM>>>(qh, ql, kh, kl, vh, vl, mask, ctxh, ctxl);

    // output projection + residual -> x1 (fp32)
    mma_gemm<1><<<gP, 256, GM_SMEM>>>(ctxh, ctxl, woh, wol, bo, x, x1, nullptr, nullptr, MROWS, DMODEL, DMODEL);

    // LN2 -> bf16 split
    ln_kernel<<<MROWS, 256>>>(x1, ln2_g, ln2_b, h2h, h2l);

    // FFN up + GELU -> ffn bf16 hi/lo
    dim3 gF1(DFF/128, MROWS/128);
    mma_gemm<2><<<gF1, 256, GM_SMEM>>>(h2h, h2l, w1h, w1l, b1, nullptr, nullptr, ffnh, ffnl, MROWS, DFF, DMODEL);

    // FFN down + residual -> out (fp32)
    dim3 gF2(DMODEL/128, MROWS/128);
    mma_gemm<1><<<gF2, 256, GM_SMEM>>>(ffnh, ffnl, w2h, w2l, b2, x1, out, nullptr, nullptr, MROWS, DMODEL, DFF);
}

// round 9
// speedup vs baseline: 1.5578x; 1.5578x over previous
#include <cuda_runtime.h>
#include <cuda_bf16.h>
#include <math.h>

// ---------------------------------------------------------------------------
// TransformerEncoderBlock: B=4, S=2048, D=1024, H=16, Dk=64, Dff=4096, fp32.
// Round 9: exact R4 GEMM kernel (known-good 2823us config) + fused QKV GEMM
// (N=3072, concatenated weights) + launch order exposing the GEMM to ncu.
// Attention reads fused QKV buffer (stride 3072). Otherwise R4 verbatim.
// ---------------------------------------------------------------------------

#define BATCH   4
#define SEQ     2048
#define DMODEL  1024
#define NHEADS  16
#define DK      64
#define DFF     4096
#define MROWS   (BATCH * SEQ)   // 8192
#define QKVN    3072            // fused QKV width

#define LDS_K   24              // GEMM smem pad (R4)

// ---------------- scratch (__device__ globals; no allocs allowed) ----------
__device__ float g_x1[MROWS * DMODEL];
__device__ float g_bqkv[QKVN];

__device__ __align__(16) __nv_bfloat16 g_hh  [MROWS * DMODEL];
__device__ __align__(16) __nv_bfloat16 g_hl  [MROWS * DMODEL];
__device__ __align__(16) __nv_bfloat16 g_qkvh[MROWS * QKVN];
__device__ __align__(16) __nv_bfloat16 g_qkvl[MROWS * QKVN];
__device__ __align__(16) __nv_bfloat16 g_ctxh[MROWS * DMODEL];
__device__ __align__(16) __nv_bfloat16 g_ctxl[MROWS * DMODEL];
__device__ __align__(16) __nv_bfloat16 g_h2h [MROWS * DMODEL];
__device__ __align__(16) __nv_bfloat16 g_h2l [MROWS * DMODEL];
__device__ __align__(16) __nv_bfloat16 g_ffnh[MROWS * DFF];
__device__ __align__(16) __nv_bfloat16 g_ffnl[MROWS * DFF];

__device__ __align__(16) __nv_bfloat16 g_wqkvh[QKVN*DMODEL], g_wqkvl[QKVN*DMODEL];
__device__ __align__(16) __nv_bfloat16 g_woh[DMODEL*DMODEL], g_wol[DMODEL*DMODEL];
__device__ __align__(16) __nv_bfloat16 g_w1h[DFF*DMODEL],    g_w1l[DFF*DMODEL];
__device__ __align__(16) __nv_bfloat16 g_w2h[DMODEL*DFF],    g_w2l[DMODEL*DFF];

// ---------------------------------------------------------------------------
__device__ __forceinline__ void split_bf16(float v, __nv_bfloat16& hi, __nv_bfloat16& lo) {
    hi = __float2bfloat16(v);
    lo = __float2bfloat16(v - __bfloat162float(hi));
}
__device__ __forceinline__ float gelu_exact(float x) {
    return 0.5f * x * (1.0f + erff(x * 0.70710678118654752f));
}
__device__ __forceinline__ void cp16(const void* dst_smem, const void* src) {
    unsigned s = (unsigned)__cvta_generic_to_shared(dst_smem);
    asm volatile("cp.async.cg.shared.global [%0], [%1], 16;\n" :: "r"(s), "l"(src));
}
__device__ __forceinline__ void mma_bf16(float* c, const unsigned* a, const unsigned* b) {
    asm volatile(
        "mma.sync.aligned.m16n8k16.row.col.f32.bf16.bf16.f32 "
        "{%0,%1,%2,%3}, {%4,%5,%6,%7}, {%8,%9}, {%0,%1,%2,%3};\n"
        : "+f"(c[0]), "+f"(c[1]), "+f"(c[2]), "+f"(c[3])
        : "r"(a[0]), "r"(a[1]), "r"(a[2]), "r"(a[3]), "r"(b[0]), "r"(b[1]));
}
__device__ __forceinline__ void ldsm4(unsigned& r0, unsigned& r1, unsigned& r2, unsigned& r3, unsigned addr) {
    asm volatile("ldmatrix.sync.aligned.m8n8.x4.shared.b16 {%0,%1,%2,%3}, [%4];"
                 : "=r"(r0), "=r"(r1), "=r"(r2), "=r"(r3) : "r"(addr));
}
__device__ __forceinline__ void ldsm4t(unsigned& r0, unsigned& r1, unsigned& r2, unsigned& r3, unsigned addr) {
    asm volatile("ldmatrix.sync.aligned.m8n8.x4.trans.shared.b16 {%0,%1,%2,%3}, [%4];"
                 : "=r"(r0), "=r"(r1), "=r"(r2), "=r"(r3) : "r"(addr));
}
// FFMA-only e^x for x <= 0 (clamped). rel err ~4e-5.
__device__ __forceinline__ float fexp(float x) {
    x = fmaxf(x, -60.0f);
    float t = x * 1.4426950408889634f;
    float z = t + 12582912.0f;
    int   e = __float_as_int(z) - 0x4B400000;
    float f = t - (z - 12582912.0f);
    float p = 0.0096181291f;
    p = fmaf(p, f, 0.0555041087f);
    p = fmaf(p, f, 0.2402265070f);
    p = fmaf(p, f, 0.6931471806f);
    p = fmaf(p, f, 1.0f);
    return __int_as_float(__float_as_int(p) + (e << 23));
}
__device__ __forceinline__ void pack_hilo(float a, float b, unsigned& hi, unsigned& lo) {
    __nv_bfloat162 h2 = __float22bfloat162_rn(make_float2(a, b));
    float2 hf = __bfloat1622float2(h2);
    __nv_bfloat162 l2 = __float22bfloat162_rn(make_float2(a - hf.x, b - hf.y));
    hi = *(unsigned*)&h2;
    lo = *(unsigned*)&l2;
}

// ---------------------------------------------------------------------------
// bias concat: [bq | bk | bv] -> g_bqkv
// ---------------------------------------------------------------------------
__global__ __launch_bounds__(256) void bias_concat_kernel(
    const float* __restrict__ a, const float* __restrict__ b,
    const float* __restrict__ c, float* __restrict__ o)
{
    int i = blockIdx.x * 256 + threadIdx.x;
    float v = (i < DMODEL) ? a[i] : (i < 2*DMODEL) ? b[i - DMODEL] : c[i - 2*DMODEL];
    o[i] = v;
}

// ---------------------------------------------------------------------------
// Weight split + transpose:  W[K][N] fp32  ->  Th/Tl[N][K] bf16
// ---------------------------------------------------------------------------
__global__ __launch_bounds__(256) void wsplit_kernel(
    const float* __restrict__ W, __nv_bfloat16* __restrict__ Th,
    __nv_bfloat16* __restrict__ Tl, int K, int N)
{
    __shared__ float tile[32][33];
    int n0 = blockIdx.x * 32, k0 = blockIdx.y * 32;
    int tx = threadIdx.x & 31;
    int ty = threadIdx.x >> 5;
    #pragma unroll
    for (int i = 0; i < 32; i += 8)
        tile[ty + i][tx] = W[(size_t)(k0 + ty + i) * N + n0 + tx];
    __syncthreads();
    #pragma unroll
    for (int i = 0; i < 32; i += 8) {
        float v = tile[tx][ty + i];
        __nv_bfloat16 hi, lo; split_bf16(v, hi, lo);
        size_t o = (size_t)(n0 + ty + i) * K + k0 + tx;
        Th[o] = hi; Tl[o] = lo;
    }
}

// ---------------------------------------------------------------------------
// LayerNorm -> bf16 hi/lo outputs.
// ---------------------------------------------------------------------------
__global__ __launch_bounds__(256) void ln_kernel(
    const float* __restrict__ x, const float* __restrict__ gamma,
    const float* __restrict__ beta,
    __nv_bfloat16* __restrict__ out_hi, __nv_bfloat16* __restrict__ out_lo)
{
    int row = blockIdx.x;
    int tid = threadIdx.x;
    const float4* xr = (const float4*)(x + (size_t)row * DMODEL);
    float4 v = xr[tid];

    __shared__ float red[256];
    red[tid] = v.x + v.y + v.z + v.w; __syncthreads();
    #pragma unroll
    for (int off = 128; off > 0; off >>= 1) {
        if (tid < off) red[tid] += red[tid + off];
        __syncthreads();
    }
    float mu = red[0] * (1.0f / DMODEL);
    __syncthreads();

    float dx0 = v.x - mu, dx1 = v.y - mu, dx2 = v.z - mu, dx3 = v.w - mu;
    red[tid] = dx0*dx0 + dx1*dx1 + dx2*dx2 + dx3*dx3; __syncthreads();
    #pragma unroll
    for (int off = 128; off > 0; off >>= 1) {
        if (tid < off) red[tid] += red[tid + off];
        __syncthreads();
    }
    float rs = rsqrtf(red[0] * (1.0f / DMODEL) + 1e-5f);

    float4 g4 = ((const float4*)gamma)[tid];
    float4 b4 = ((const float4*)beta)[tid];
    float o0 = dx0 * rs * g4.x + b4.x;
    float o1 = dx1 * rs * g4.y + b4.y;
    float o2 = dx2 * rs * g4.z + b4.z;
    float o3 = dx3 * rs * g4.w + b4.w;

    unsigned h01, l01, h23, l23;
    pack_hilo(o0, o1, h01, l01);
    pack_hilo(o2, o3, h23, l23);
    size_t o = (size_t)row * DMODEL + tid * 4;
    *(unsigned*)&out_hi[o]   = h01; *(unsigned*)&out_hi[o+2] = h23;
    *(unsigned*)&out_lo[o]   = l01; *(unsigned*)&out_lo[o+2] = l23;
}

// ---------------------------------------------------------------------------
// bf16x3 MMA GEMM (R4 verbatim): C = (Ah+Al)[M,K] @ (Bh+Bl)^T[N,K] + bias...
// CTA 128x128xBK16, 8 warps (2x4), warp tile 64x32, m16n8k16 mma.
// EPI: 1 bias+R->f32 | 2 bias+gelu->bf16 hi/lo | 3 bias->bf16 hi/lo
// ---------------------------------------------------------------------------
template<int EPI>
__global__ __launch_bounds__(256) void mma_gemm(
    const __nv_bfloat16* __restrict__ Ah, const __nv_bfloat16* __restrict__ Al,
    const __nv_bfloat16* __restrict__ Bh, const __nv_bfloat16* __restrict__ Bl,
    const float* __restrict__ bias, const float* __restrict__ R,
    float* __restrict__ C, __nv_bfloat16* __restrict__ Chi,
    __nv_bfloat16* __restrict__ Clo, int M, int N, int K)
{
    __shared__ __align__(16) __nv_bfloat16 smem[2][4][128 * LDS_K];

    const int tid = threadIdx.x;
    const int bm = blockIdx.y * 128;
    const int bn = blockIdx.x * 128;

    const int lrow  = tid >> 1;
    const int lhalf = tid & 1;
    const __nv_bfloat16* src0 = Ah + (size_t)(bm + lrow) * K + lhalf * 8;
    const __nv_bfloat16* src1 = Al + (size_t)(bm + lrow) * K + lhalf * 8;
    const __nv_bfloat16* src2 = Bh + (size_t)(bn + lrow) * K + lhalf * 8;
    const __nv_bfloat16* src3 = Bl + (size_t)(bn + lrow) * K + lhalf * 8;
    const int sdst = lrow * LDS_K + lhalf * 8;

    const int warp  = tid >> 5;
    const int lane  = tid & 31;
    const int warpm = warp >> 2;
    const int warpn = warp & 3;
    const int g = lane >> 2;
    const int c = lane & 3;

    float acc[4][4][4];
    #pragma unroll
    for (int i = 0; i < 4; i++)
        #pragma unroll
        for (int j = 0; j < 4; j++)
            #pragma unroll
            for (int r = 0; r < 4; r++) acc[i][j][r] = 0.0f;

    const int nk = K >> 4;

    cp16(&smem[0][0][sdst], src0);
    cp16(&smem[0][1][sdst], src1);
    cp16(&smem[0][2][sdst], src2);
    cp16(&smem[0][3][sdst], src3);
    asm volatile("cp.async.commit_group;\n" ::);

    for (int t = 0; t < nk; t++) {
        asm volatile("cp.async.wait_group 0;\n" ::);
        __syncthreads();
        if (t + 1 < nk) {
            int ko = (t + 1) << 4;
            int s = (t + 1) & 1;
            cp16(&smem[s][0][sdst], src0 + ko);
            cp16(&smem[s][1][sdst], src1 + ko);
            cp16(&smem[s][2][sdst], src2 + ko);
            cp16(&smem[s][3][sdst], src3 + ko);
            asm volatile("cp.async.commit_group;\n" ::);
        }

        const __nv_bfloat16* sAh = smem[t & 1][0];
        const __nv_bfloat16* sAl = smem[t & 1][1];
        const __nv_bfloat16* sBh = smem[t & 1][2];
        const __nv_bfloat16* sBl = smem[t & 1][3];

        unsigned ah[4][4], al[4][4], bh[4][2], bl[4][2];
        const int abase = (warpm * 64 + g) * LDS_K + c * 2;
        const int bbase = (warpn * 32 + g) * LDS_K + c * 2;

        #pragma unroll
        for (int mi = 0; mi < 4; mi++) {
            int o = abase + mi * 16 * LDS_K;
            ah[mi][0] = *(const unsigned*)(sAh + o);
            ah[mi][1] = *(const unsigned*)(sAh + o + 8 * LDS_K);
            ah[mi][2] = *(const unsigned*)(sAh + o + 8);
            ah[mi][3] = *(const unsigned*)(sAh + o + 8 * LDS_K + 8);
        }
        #pragma unroll
        for (int ni = 0; ni < 4; ni++) {
            int o = bbase + ni * 8 * LDS_K;
            bh[ni][0] = *(const unsigned*)(sBh + o);
            bh[ni][1] = *(const unsigned*)(sBh + o + 8);
        }
        #pragma unroll
        for (int mi = 0; mi < 4; mi++)
            #pragma unroll
            for (int ni = 0; ni < 4; ni++)
                mma_bf16(acc[mi][ni], ah[mi], bh[ni]);
        #pragma unroll
        for (int mi = 0; mi < 4; mi++) {
            int o = abase + mi * 16 * LDS_K;
            al[mi][0] = *(const unsigned*)(sAl + o);
            al[mi][1] = *(const unsigned*)(sAl + o + 8 * LDS_K);
            al[mi][2] = *(const unsigned*)(sAl + o + 8);
            al[mi][3] = *(const unsigned*)(sAl + o + 8 * LDS_K + 8);
        }
        #pragma unroll
        for (int mi = 0; mi < 4; mi++)
            #pragma unroll
            for (int ni = 0; ni < 4; ni++)
                mma_bf16(acc[mi][ni], al[mi], bh[ni]);
        #pragma unroll
        for (int ni = 0; ni < 4; ni++) {
            int o = bbase + ni * 8 * LDS_K;
            bl[ni][0] = *(const unsigned*)(sBl + o);
            bl[ni][1] = *(const unsigned*)(sBl + o + 8);
        }
        #pragma unroll
        for (int mi = 0; mi < 4; mi++)
            #pragma unroll
            for (int ni = 0; ni < 4; ni++)
                mma_bf16(acc[mi][ni], ah[mi], bl[ni]);
    }

    #pragma unroll
    for (int mi = 0; mi < 4; mi++) {
        int r0 = bm + warpm * 64 + mi * 16 + g;
        #pragma unroll
        for (int ni = 0; ni < 4; ni++) {
            int col = bn + warpn * 32 + ni * 8 + c * 2;
            float2 bia = *(const float2*)&bias[col];
            float v0 = acc[mi][ni][0] + bia.x;
            float v1 = acc[mi][ni][1] + bia.y;
            float v2 = acc[mi][ni][2] + bia.x;
            float v3 = acc[mi][ni][3] + bia.y;
            size_t o0 = (size_t)r0 * N + col;
            size_t o1 = (size_t)(r0 + 8) * N + col;
            if (EPI == 1) {
                float2 ra = *(const float2*)&R[o0];
                float2 rb = *(const float2*)&R[o1];
                v0 += ra.x; v1 += ra.y; v2 += rb.x; v3 += rb.y;
                *(float2*)&C[o0] = make_float2(v0, v1);
                *(float2*)&C[o1] = make_float2(v2, v3);
            } else {
                if (EPI == 2) {
                    v0 = gelu_exact(v0); v1 = gelu_exact(v1);
                    v2 = gelu_exact(v2); v3 = gelu_exact(v3);
                }
                unsigned h01, l01, h23, l23;
                pack_hilo(v0, v1, h01, l01);
                pack_hilo(v2, v3, h23, l23);
                *(unsigned*)&Chi[o0] = h01; *(unsigned*)&Chi[o1] = h23;
                *(unsigned*)&Clo[o0] = l01; *(unsigned*)&Clo[o1] = l23;
            }
        }
    }
}

// ---------------------------------------------------------------------------
// Tensor-core flash attention (R4 structure; reads fused QKV, stride 3072).
// ---------------------------------------------------------------------------
#define ATT_QH   0
#define ATT_QL   8192
#define ATT_KH   16384
#define ATT_TILE 8192
#define ATT_FM   (16384 + 2*32768)
#define ATT_SMEM (ATT_FM + 2*64*4)
#define OFF_K    DMODEL
#define OFF_V    (2*DMODEL)

__device__ __forceinline__ unsigned swz(unsigned base, int row, int cc) {
    return base + (unsigned)((row << 7) + (((cc ^ row) & 7) << 4));
}

__global__ __launch_bounds__(128) void attn_mma(
    const __nv_bfloat16* __restrict__ QKVh, const __nv_bfloat16* __restrict__ QKVl,
    const int* __restrict__ mask,
    __nv_bfloat16* __restrict__ Ohi, __nv_bfloat16* __restrict__ Olo)
{
    extern __shared__ __align__(16) char sm[];
    const unsigned smb = (unsigned)__cvta_generic_to_shared(sm);
    float* fmask = (float*)(sm + ATT_FM);

    const int b  = blockIdx.z;
    const int h  = blockIdx.y;
    const int qt = blockIdx.x;
    const int tid  = threadIdx.x;
    const int warp = tid >> 5;
    const int lane = tid & 31;
    const int li  = lane & 7;
    const int grp = lane >> 3;
    const int g = lane >> 2;
    const int c = lane & 3;

    const int qrow0 = qt * 64;
    const size_t rowQ = (size_t)(b * SEQ + qrow0);

    {
        #pragma unroll
        for (int i = 0; i < 4; i++) {
            int idx = tid + i * 128;
            int row = idx >> 3, cc = idx & 7;
            size_t gq = (rowQ + row) * QKVN + h * DK + cc * 8;
            cp16(sm + swz(ATT_QH, row, cc), QKVh + gq);
            cp16(sm + swz(ATT_QL, row, cc), QKVl + gq);
        }
        #pragma unroll
        for (int i = 0; i < 4; i++) {
            int idx = tid + i * 128;
            int row = idx >> 3, cc = idx & 7;
            size_t gr = (size_t)(b * SEQ + row) * QKVN + h * DK + cc * 8;
            cp16(sm + swz(ATT_KH, row, cc), QKVh + gr + OFF_K);
            cp16(sm + swz(ATT_KH + ATT_TILE, row, cc), QKVl + gr + OFF_K);
            cp16(sm + swz(ATT_KH + 2*ATT_TILE, row, cc), QKVh + gr + OFF_V);
            cp16(sm + swz(ATT_KH + 3*ATT_TILE, row, cc), QKVl + gr + OFF_V);
        }
        if (tid < 64) fmask[tid] = (mask[b * SEQ + tid] != 0) ? 0.0f : -1e30f;
        asm volatile("cp.async.commit_group;\n" ::);
    }

    float oacc[8][4];
    #pragma unroll
    for (int nt = 0; nt < 8; nt++)
        #pragma unroll
        for (int r = 0; r < 4; r++) oacc[nt][r] = 0.0f;
    float m0 = -1e30f, m1 = -1e30f, l0 = 0.0f, l1 = 0.0f;
    unsigned qfh[4][4], qfl[4][4];

    const int NT = SEQ / 64;
    for (int kt = 0; kt < NT; kt++) {
        asm volatile("cp.async.wait_group 0;\n" ::);
        __syncthreads();

        if (kt == 0) {
            int qrow = warp * 16 + ((grp & 1) << 3) + li;
            #pragma unroll
            for (int q = 0; q < 4; q++) {
                int cc = 2 * q + (grp >> 1);
                ldsm4(qfh[q][0], qfh[q][1], qfh[q][2], qfh[q][3], smb + swz(ATT_QH, qrow, cc));
                ldsm4(qfl[q][0], qfl[q][1], qfl[q][2], qfl[q][3], smb + swz(ATT_QL, qrow, cc));
            }
        }

        if (kt + 1 < NT) {
            int s = (kt + 1) & 1;
            int kb = (kt + 1) * 64;
            #pragma unroll
            for (int i = 0; i < 4; i++) {
                int idx = tid + i * 128;
                int row = idx >> 3, cc = idx & 7;
                size_t gr = (size_t)(b * SEQ + kb + row) * QKVN + h * DK + cc * 8;
                cp16(sm + swz(ATT_KH + s*32768, row, cc), QKVh + gr + OFF_K);
                cp16(sm + swz(ATT_KH + s*32768 + ATT_TILE, row, cc), QKVl + gr + OFF_K);
                cp16(sm + swz(ATT_KH + s*32768 + 2*ATT_TILE, row, cc), QKVh + gr + OFF_V);
                cp16(sm + swz(ATT_KH + s*32768 + 3*ATT_TILE, row, cc), QKVl + gr + OFF_V);
            }
            if (tid < 64) fmask[s * 64 + tid] = (mask[b * SEQ + kb + tid] != 0) ? 0.0f : -1e30f;
            asm volatile("cp.async.commit_group;\n" ::);
        }

        const int s = kt & 1;
        const unsigned KHb = ATT_KH + s*32768;
        const unsigned KLb = KHb + ATT_TILE;
        const unsigned VHb = KHb + 2*ATT_TILE;
        const unsigned VLb = KHb + 3*ATT_TILE;
        const float* fm = fmask + s * 64;

        float sacc[8][4];
        #pragma unroll
        for (int nt = 0; nt < 8; nt++)
            #pragma unroll
            for (int r = 0; r < 4; r++) sacc[nt][r] = 0.0f;

        {
            const int krow = ((grp >> 1) << 3) + li;
            const int kccb = grp & 1;
            #pragma unroll
            for (int q = 0; q < 4; q++) {
                unsigned kb2[8][2];
                #pragma unroll
                for (int p = 0; p < 4; p++)
                    ldsm4(kb2[2*p][0], kb2[2*p][1], kb2[2*p+1][0], kb2[2*p+1][1],
                          smb + swz(KHb, 16*p + krow, 2*q + kccb));
                #pragma unroll
                for (int nt = 0; nt < 8; nt++) mma_bf16(sacc[nt], qfh[q], kb2[nt]);
                #pragma unroll
                for (int nt = 0; nt < 8; nt++) mma_bf16(sacc[nt], qfl[q], kb2[nt]);
                #pragma unroll
                for (int p = 0; p < 4; p++)
                    ldsm4(kb2[2*p][0], kb2[2*p][1], kb2[2*p+1][0], kb2[2*p+1][1],
                          smb + swz(KLb, 16*p + krow, 2*q + kccb));
                #pragma unroll
                for (int nt = 0; nt < 8; nt++) mma_bf16(sacc[nt], qfh[q], kb2[nt]);
            }
        }

        float mx0 = -1e30f, mx1 = -1e30f;
        #pragma unroll
        for (int nt = 0; nt < 8; nt++) {
            float f0 = fm[nt*8 + 2*c];
            float f1 = fm[nt*8 + 2*c + 1];
            sacc[nt][0] = fmaf(sacc[nt][0], 0.125f, f0);
            sacc[nt][1] = fmaf(sacc[nt][1], 0.125f, f1);
            sacc[nt][2] = fmaf(sacc[nt][2], 0.125f, f0);
            sacc[nt][3] = fmaf(sacc[nt][3], 0.125f, f1);
            mx0 = fmaxf(mx0, fmaxf(sacc[nt][0], sacc[nt][1]));
            mx1 = fmaxf(mx1, fmaxf(sacc[nt][2], sacc[nt][3]));
        }
        mx0 = fmaxf(mx0, __shfl_xor_sync(0xffffffff, mx0, 1));
        mx0 = fmaxf(mx0, __shfl_xor_sync(0xffffffff, mx0, 2));
        mx1 = fmaxf(mx1, __shfl_xor_sync(0xffffffff, mx1, 1));
        mx1 = fmaxf(mx1, __shfl_xor_sync(0xffffffff, mx1, 2));

        float nm0 = fmaxf(m0, mx0), nm1 = fmaxf(m1, mx1);
        float sc0 = fexp(m0 - nm0), sc1 = fexp(m1 - nm1);
        m0 = nm0; m1 = nm1;
        l0 *= sc0; l1 *= sc1;
        #pragma unroll
        for (int nt = 0; nt < 8; nt++) {
            oacc[nt][0] *= sc0; oacc[nt][1] *= sc0;
            oacc[nt][2] *= sc1; oacc[nt][3] *= sc1;
        }

        float ls0 = 0.0f, ls1 = 0.0f;
        #pragma unroll
        for (int nt = 0; nt < 8; nt++) {
            float p0 = fexp(sacc[nt][0] - nm0);
            float p1 = fexp(sacc[nt][1] - nm0);
            float p2 = fexp(sacc[nt][2] - nm1);
            float p3 = fexp(sacc[nt][3] - nm1);
            sacc[nt][0] = p0; sacc[nt][1] = p1; sacc[nt][2] = p2; sacc[nt][3] = p3;
            ls0 += p0 + p1; ls1 += p2 + p3;
        }
        ls0 += __shfl_xor_sync(0xffffffff, ls0, 1);
        ls0 += __shfl_xor_sync(0xffffffff, ls0, 2);
        ls1 += __shfl_xor_sync(0xffffffff, ls1, 1);
        ls1 += __shfl_xor_sync(0xffffffff, ls1, 2);
        l0 += ls0; l1 += ls1;

        unsigned pfh[4][4], pfl[4][4];
        #pragma unroll
        for (int j = 0; j < 4; j++) {
            pack_hilo(sacc[2*j][0],   sacc[2*j][1],   pfh[j][0], pfl[j][0]);
            pack_hilo(sacc[2*j][2],   sacc[2*j][3],   pfh[j][1], pfl[j][1]);
            pack_hilo(sacc[2*j+1][0], sacc[2*j+1][1], pfh[j][2], pfl[j][2]);
            pack_hilo(sacc[2*j+1][2], sacc[2*j+1][3], pfh[j][3], pfl[j][3]);
        }

        {
            const int vrow = ((grp & 1) << 3) + li;
            const int vccb = grp >> 1;
            #pragma unroll
            for (int j = 0; j < 4; j++) {
                unsigned vb2[8][2];
                #pragma unroll
                for (int d = 0; d < 8; d += 2)
                    ldsm4t(vb2[d][0], vb2[d][1], vb2[d+1][0], vb2[d+1][1],
                           smb + swz(VHb, 16*j + vrow, d + vccb));
                #pragma unroll
                for (int nt = 0; nt < 8; nt++) mma_bf16(oacc[nt], pfh[j], vb2[nt]);
                #pragma unroll
                for (int nt = 0; nt < 8; nt++) mma_bf16(oacc[nt], pfl[j], vb2[nt]);
                #pragma unroll
                for (int d = 0; d < 8; d += 2)
                    ldsm4t(vb2[d][0], vb2[d][1], vb2[d+1][0], vb2[d+1][1],
                           smb + swz(VLb, 16*j + vrow, d + vccb));
                #pragma unroll
                for (int nt = 0; nt < 8; nt++) mma_bf16(oacc[nt], pfh[j], vb2[nt]);
            }
        }
    }

    float inv0 = 1.0f / l0, inv1 = 1.0f / l1;
    int r0 = qrow0 + warp * 16 + g;
    int r1 = r0 + 8;
    size_t base0 = (size_t)(b * SEQ + r0) * DMODEL + h * DK;
    size_t base1 = (size_t)(b * SEQ + r1) * DMODEL + h * DK;
    #pragma unroll
    for (int nt = 0; nt < 8; nt++) {
        int col = nt * 8 + 2 * c;
        unsigned hi0, lo0, hi1, lo1;
        pack_hilo(oacc[nt][0] * inv0, oacc[nt][1] * inv0, hi0, lo0);
        pack_hilo(oacc[nt][2] * inv1, oacc[nt][3] * inv1, hi1, lo1);
        *(unsigned*)&Ohi[base0 + col] = hi0;
        *(unsigned*)&Olo[base0 + col] = lo0;
        *(unsigned*)&Ohi[base1 + col] = hi1;
        *(unsigned*)&Olo[base1 + col] = lo1;
    }
}

// ---------------------------------------------------------------------------
// Host launch (launch 5 = fused QKV GEMM -> captured by ncu -s 5 -c 1)
// ---------------------------------------------------------------------------
extern "C" void kernel_launch(void* const* d_in, const int* in_sizes, int n_in,
                              void* d_out, int out_size)
{
    const float* x     = (const float*)d_in[0];
    const int*   mask  = (const int*)  d_in[1];
    const float* Wq    = (const float*)d_in[2];
    const float* bq    = (const float*)d_in[3];
    const float* Wk    = (const float*)d_in[4];
    const float* bk    = (const float*)d_in[5];
    const float* Wv    = (const float*)d_in[6];
    const float* bv    = (const float*)d_in[7];
    const float* Wo    = (const float*)d_in[8];
    const float* bo    = (const float*)d_in[9];
    const float* W1    = (const float*)d_in[10];
    const float* b1    = (const float*)d_in[11];
    const float* W2    = (const float*)d_in[12];
    const float* b2    = (const float*)d_in[13];
    const float* ln1_g = (const float*)d_in[14];
    const float* ln1_b = (const float*)d_in[15];
    const float* ln2_g = (const float*)d_in[16];
    const float* ln2_b = (const float*)d_in[17];
    float* out = (float*)d_out;

    float *x1, *bqkv;
    __nv_bfloat16 *hh, *hl, *qkvh, *qkvl, *ctxh, *ctxl, *h2h, *h2l, *ffnh, *ffnl;
    __nv_bfloat16 *wqkvh, *wqkvl, *woh, *wol, *w1h, *w1l, *w2h, *w2l;
    cudaGetSymbolAddress((void**)&x1,   g_x1);
    cudaGetSymbolAddress((void**)&bqkv, g_bqkv);
    cudaGetSymbolAddress((void**)&hh,   g_hh);
    cudaGetSymbolAddress((void**)&hl,   g_hl);
    cudaGetSymbolAddress((void**)&qkvh, g_qkvh);
    cudaGetSymbolAddress((void**)&qkvl, g_qkvl);
    cudaGetSymbolAddress((void**)&ctxh, g_ctxh);
    cudaGetSymbolAddress((void**)&ctxl, g_ctxl);
    cudaGetSymbolAddress((void**)&h2h,  g_h2h);
    cudaGetSymbolAddress((void**)&h2l,  g_h2l);
    cudaGetSymbolAddress((void**)&ffnh, g_ffnh);
    cudaGetSymbolAddress((void**)&ffnl, g_ffnl);
    cudaGetSymbolAddress((void**)&wqkvh, g_wqkvh);
    cudaGetSymbolAddress((void**)&wqkvl, g_wqkvl);
    cudaGetSymbolAddress((void**)&woh,  g_woh); cudaGetSymbolAddress((void**)&wol, g_wol);
    cudaGetSymbolAddress((void**)&w1h,  g_w1h); cudaGetSymbolAddress((void**)&w1l, g_w1l);
    cudaGetSymbolAddress((void**)&w2h,  g_w2h); cudaGetSymbolAddress((void**)&w2l, g_w2l);

    cudaFuncSetAttribute(attn_mma, cudaFuncAttributeMaxDynamicSharedMemorySize, ATT_SMEM);

    dim3 gW(DMODEL/32, DMODEL/32);

    // launch 0: bias concat
    bias_concat_kernel<<<QKVN/256, 256>>>(bq, bk, bv, bqkv);
    // launches 1-3: QKV weight splits into fused [3072][1024]
    wsplit_kernel<<<gW, 256>>>(Wq, wqkvh,                      wqkvl,                      DMODEL, DMODEL);
    wsplit_kernel<<<gW, 256>>>(Wk, wqkvh + DMODEL*DMODEL,      wqkvl + DMODEL*DMODEL,      DMODEL, DMODEL);
    wsplit_kernel<<<gW, 256>>>(Wv, wqkvh + 2*DMODEL*DMODEL,    wqkvl + 2*DMODEL*DMODEL,    DMODEL, DMODEL);
    // launch 4: LN1
    ln_kernel<<<MROWS, 256>>>(x, ln1_g, ln1_b, hh, hl);

    // launch 5: fused QKV projection (ncu captures this)
    dim3 gQKV(QKVN/128, MROWS/128);   // (24, 64)
    mma_gemm<3><<<gQKV, 256>>>(hh, hl, wqkvh, wqkvl, bqkv, nullptr, nullptr,
                               qkvh, qkvl, MROWS, QKVN, DMODEL);

    // remaining weight splits
    wsplit_kernel<<<gW, 256>>>(Wo, woh, wol, DMODEL, DMODEL);
    dim3 gW1(DFF/32, DMODEL/32);
    wsplit_kernel<<<gW1, 256>>>(W1, w1h, w1l, DMODEL, DFF);
    dim3 gW2(DMODEL/32, DFF/32);
    wsplit_kernel<<<gW2, 256>>>(W2, w2h, w2l, DFF, DMODEL);

    // attention -> ctx bf16 hi/lo
    dim3 gA(SEQ/64, NHEADS, BATCH);
    attn_mma<<<gA, 128, ATT_SMEM>>>(qkvh, qkvl, mask, ctxh, ctxl);

    // output projection + residual -> x1 (fp32)
    dim3 gP(DMODEL/128, MROWS/128);
    mma_gemm<1><<<gP, 256>>>(ctxh, ctxl, woh, wol, bo, x, x1, nullptr, nullptr, MROWS, DMODEL, DMODEL);

    // LN2 -> bf16 split
    ln_kernel<<<MROWS, 256>>>(x1, ln2_g, ln2_b, h2h, h2l);

    // FFN up + GELU -> ffn bf16 hi/lo
    dim3 gF1(DFF/128, MROWS/128);
    mma_gemm<2><<<gF1, 256>>>(h2h, h2l, w1h, w1l, b1, nullptr, nullptr, ffnh, ffnl, MROWS, DFF, DMODEL);

    // FFN down + residual -> out (fp32)
    dim3 gF2(DMODEL/128, MROWS/128);
    mma_gemm<1><<<gF2, 256>>>(ffnh, ffnl, w2h, w2l, b2, x1, out, nullptr, nullptr, MROWS, DMODEL, DFF);
}

// round 10
// speedup vs baseline: 1.9520x; 1.2531x over previous
#include <cuda_runtime.h>
#include <cuda_fp16.h>
#include <math.h>

// ---------------------------------------------------------------------------
// TransformerEncoderBlock: B=4, S=2048, D=1024, H=16, Dk=64, Dff=4096, fp32.
// Round 10: fp16 2-term split (activations hi/lo fp16, weights hi-only fp16)
// -> 2 MMAs per k-step instead of 3, 3 smem tiles instead of 4.
// GEMM loop body = R4 structure minus the bl section. Attention likewise
// drops Kl/Vl. Expected rel_err ~2e-4 (fp16 unit roundoff 2^-12 on B side).
// ---------------------------------------------------------------------------

#define BATCH   4
#define SEQ     2048
#define DMODEL  1024
#define NHEADS  16
#define DK      64
#define DFF     4096
#define MROWS   (BATCH * SEQ)   // 8192
#define QKVN    3072            // fused QKV width

#define LDS_K   24              // GEMM smem pad (R4)

// ---------------- scratch (__device__ globals; no allocs allowed) ----------
__device__ float g_x1[MROWS * DMODEL];
__device__ float g_bqkv[QKVN];

__device__ __align__(16) __half g_hh  [MROWS * DMODEL];
__device__ __align__(16) __half g_hl  [MROWS * DMODEL];
__device__ __align__(16) __half g_qkvh[MROWS * QKVN];
__device__ __align__(16) __half g_qkvl[MROWS * QKVN];
__device__ __align__(16) __half g_ctxh[MROWS * DMODEL];
__device__ __align__(16) __half g_ctxl[MROWS * DMODEL];
__device__ __align__(16) __half g_h2h [MROWS * DMODEL];
__device__ __align__(16) __half g_h2l [MROWS * DMODEL];
__device__ __align__(16) __half g_ffnh[MROWS * DFF];
__device__ __align__(16) __half g_ffnl[MROWS * DFF];

__device__ __align__(16) __half g_wqkvh[QKVN*DMODEL];
__device__ __align__(16) __half g_woh[DMODEL*DMODEL];
__device__ __align__(16) __half g_w1h[DFF*DMODEL];
__device__ __align__(16) __half g_w2h[DMODEL*DFF];

// ---------------------------------------------------------------------------
__device__ __forceinline__ float gelu_exact(float x) {
    return 0.5f * x * (1.0f + erff(x * 0.70710678118654752f));
}
__device__ __forceinline__ void cp16(const void* dst_smem, const void* src) {
    unsigned s = (unsigned)__cvta_generic_to_shared(dst_smem);
    asm volatile("cp.async.cg.shared.global [%0], [%1], 16;\n" :: "r"(s), "l"(src));
}
__device__ __forceinline__ void mma_f16(float* c, const unsigned* a, const unsigned* b) {
    asm volatile(
        "mma.sync.aligned.m16n8k16.row.col.f32.f16.f16.f32 "
        "{%0,%1,%2,%3}, {%4,%5,%6,%7}, {%8,%9}, {%0,%1,%2,%3};\n"
        : "+f"(c[0]), "+f"(c[1]), "+f"(c[2]), "+f"(c[3])
        : "r"(a[0]), "r"(a[1]), "r"(a[2]), "r"(a[3]), "r"(b[0]), "r"(b[1]));
}
__device__ __forceinline__ void ldsm4(unsigned& r0, unsigned& r1, unsigned& r2, unsigned& r3, unsigned addr) {
    asm volatile("ldmatrix.sync.aligned.m8n8.x4.shared.b16 {%0,%1,%2,%3}, [%4];"
                 : "=r"(r0), "=r"(r1), "=r"(r2), "=r"(r3) : "r"(addr));
}
__device__ __forceinline__ void ldsm4t(unsigned& r0, unsigned& r1, unsigned& r2, unsigned& r3, unsigned addr) {
    asm volatile("ldmatrix.sync.aligned.m8n8.x4.trans.shared.b16 {%0,%1,%2,%3}, [%4];"
                 : "=r"(r0), "=r"(r1), "=r"(r2), "=r"(r3) : "r"(addr));
}
// FFMA-only e^x for x <= 0 (clamped). rel err ~4e-5.
__device__ __forceinline__ float fexp(float x) {
    x = fmaxf(x, -60.0f);
    float t = x * 1.4426950408889634f;
    float z = t + 12582912.0f;
    int   e = __float_as_int(z) - 0x4B400000;
    float f = t - (z - 12582912.0f);
    float p = 0.0096181291f;
    p = fmaf(p, f, 0.0555041087f);
    p = fmaf(p, f, 0.2402265070f);
    p = fmaf(p, f, 0.6931471806f);
    p = fmaf(p, f, 1.0f);
    return __int_as_float(__float_as_int(p) + (e << 23));
}
// pack two floats -> fp16x2 hi, and fp16x2 residual lo
__device__ __forceinline__ void pack_hilo(float a, float b, unsigned& hi, unsigned& lo) {
    __half2 h2 = __floats2half2_rn(a, b);
    float2 hf = __half22float2(h2);
    __half2 l2 = __floats2half2_rn(a - hf.x, b - hf.y);
    hi = *(unsigned*)&h2;
    lo = *(unsigned*)&l2;
}

// ---------------------------------------------------------------------------
// bias concat: [bq | bk | bv] -> g_bqkv
// ---------------------------------------------------------------------------
__global__ __launch_bounds__(256) void bias_concat_kernel(
    const float* __restrict__ a, const float* __restrict__ b,
    const float* __restrict__ c, float* __restrict__ o)
{
    int i = blockIdx.x * 256 + threadIdx.x;
    float v = (i < DMODEL) ? a[i] : (i < 2*DMODEL) ? b[i - DMODEL] : c[i - 2*DMODEL];
    o[i] = v;
}

// ---------------------------------------------------------------------------
// Weight convert + transpose:  W[K][N] fp32  ->  Th[N][K] fp16 (hi only)
// ---------------------------------------------------------------------------
__global__ __launch_bounds__(256) void wsplit_kernel(
    const float* __restrict__ W, __half* __restrict__ Th, int K, int N)
{
    __shared__ float tile[32][33];
    int n0 = blockIdx.x * 32, k0 = blockIdx.y * 32;
    int tx = threadIdx.x & 31;
    int ty = threadIdx.x >> 5;
    #pragma unroll
    for (int i = 0; i < 32; i += 8)
        tile[ty + i][tx] = W[(size_t)(k0 + ty + i) * N + n0 + tx];
    __syncthreads();
    #pragma unroll
    for (int i = 0; i < 32; i += 8) {
        float v = tile[tx][ty + i];
        Th[(size_t)(n0 + ty + i) * K + k0 + tx] = __float2half_rn(v);
    }
}

// ---------------------------------------------------------------------------
// LayerNorm -> fp16 hi/lo outputs.
// ---------------------------------------------------------------------------
__global__ __launch_bounds__(256) void ln_kernel(
    const float* __restrict__ x, const float* __restrict__ gamma,
    const float* __restrict__ beta,
    __half* __restrict__ out_hi, __half* __restrict__ out_lo)
{
    int row = blockIdx.x;
    int tid = threadIdx.x;
    const float4* xr = (const float4*)(x + (size_t)row * DMODEL);
    float4 v = xr[tid];

    __shared__ float red[256];
    red[tid] = v.x + v.y + v.z + v.w; __syncthreads();
    #pragma unroll
    for (int off = 128; off > 0; off >>= 1) {
        if (tid < off) red[tid] += red[tid + off];
        __syncthreads();
    }
    float mu = red[0] * (1.0f / DMODEL);
    __syncthreads();

    float dx0 = v.x - mu, dx1 = v.y - mu, dx2 = v.z - mu, dx3 = v.w - mu;
    red[tid] = dx0*dx0 + dx1*dx1 + dx2*dx2 + dx3*dx3; __syncthreads();
    #pragma unroll
    for (int off = 128; off > 0; off >>= 1) {
        if (tid < off) red[tid] += red[tid + off];
        __syncthreads();
    }
    float rs = rsqrtf(red[0] * (1.0f / DMODEL) + 1e-5f);

    float4 g4 = ((const float4*)gamma)[tid];
    float4 b4 = ((const float4*)beta)[tid];
    float o0 = dx0 * rs * g4.x + b4.x;
    float o1 = dx1 * rs * g4.y + b4.y;
    float o2 = dx2 * rs * g4.z + b4.z;
    float o3 = dx3 * rs * g4.w + b4.w;

    unsigned h01, l01, h23, l23;
    pack_hilo(o0, o1, h01, l01);
    pack_hilo(o2, o3, h23, l23);
    size_t o = (size_t)row * DMODEL + tid * 4;
    *(unsigned*)&out_hi[o]   = h01; *(unsigned*)&out_hi[o+2] = h23;
    *(unsigned*)&out_lo[o]   = l01; *(unsigned*)&out_lo[o+2] = l23;
}

// ---------------------------------------------------------------------------
// fp16 2-term MMA GEMM: C = (Ah+Al)[M,K] @ Bh^T[N,K] + bias (+R | gelu)
// CTA 128x128xBK16, 8 warps (2x4), warp tile 64x32, m16n8k16 mma.
// R4 loop body minus the bl section; 3 smem tiles per stage.
// EPI: 1 bias+R->f32 | 2 bias+gelu->fp16 hi/lo | 3 bias->fp16 hi/lo
// ---------------------------------------------------------------------------
template<int EPI>
__global__ __launch_bounds__(256) void mma_gemm(
    const __half* __restrict__ Ah, const __half* __restrict__ Al,
    const __half* __restrict__ Bh,
    const float* __restrict__ bias, const float* __restrict__ R,
    float* __restrict__ C, __half* __restrict__ Chi,
    __half* __restrict__ Clo, int M, int N, int K)
{
    __shared__ __align__(16) __half smem[2][3][128 * LDS_K];

    const int tid = threadIdx.x;
    const int bm = blockIdx.y * 128;
    const int bn = blockIdx.x * 128;

    const int lrow  = tid >> 1;
    const int lhalf = tid & 1;
    const __half* src0 = Ah + (size_t)(bm + lrow) * K + lhalf * 8;
    const __half* src1 = Al + (size_t)(bm + lrow) * K + lhalf * 8;
    const __half* src2 = Bh + (size_t)(bn + lrow) * K + lhalf * 8;
    const int sdst = lrow * LDS_K + lhalf * 8;

    const int warp  = tid >> 5;
    const int lane  = tid & 31;
    const int warpm = warp >> 2;
    const int warpn = warp & 3;
    const int g = lane >> 2;
    const int c = lane & 3;

    float acc[4][4][4];
    #pragma unroll
    for (int i = 0; i < 4; i++)
        #pragma unroll
        for (int j = 0; j < 4; j++)
            #pragma unroll
            for (int r = 0; r < 4; r++) acc[i][j][r] = 0.0f;

    const int nk = K >> 4;

    cp16(&smem[0][0][sdst], src0);
    cp16(&smem[0][1][sdst], src1);
    cp16(&smem[0][2][sdst], src2);
    asm volatile("cp.async.commit_group;\n" ::);

    for (int t = 0; t < nk; t++) {
        asm volatile("cp.async.wait_group 0;\n" ::);
        __syncthreads();
        if (t + 1 < nk) {
            int ko = (t + 1) << 4;
            int s = (t + 1) & 1;
            cp16(&smem[s][0][sdst], src0 + ko);
            cp16(&smem[s][1][sdst], src1 + ko);
            cp16(&smem[s][2][sdst], src2 + ko);
            asm volatile("cp.async.commit_group;\n" ::);
        }

        const __half* sAh = smem[t & 1][0];
        const __half* sAl = smem[t & 1][1];
        const __half* sBh = smem[t & 1][2];

        unsigned ah[4][4], al[4][4], bh[4][2];
        const int abase = (warpm * 64 + g) * LDS_K + c * 2;
        const int bbase = (warpn * 32 + g) * LDS_K + c * 2;

        #pragma unroll
        for (int mi = 0; mi < 4; mi++) {
            int o = abase + mi * 16 * LDS_K;
            ah[mi][0] = *(const unsigned*)(sAh + o);
            ah[mi][1] = *(const unsigned*)(sAh + o + 8 * LDS_K);
            ah[mi][2] = *(const unsigned*)(sAh + o + 8);
            ah[mi][3] = *(const unsigned*)(sAh + o + 8 * LDS_K + 8);
        }
        #pragma unroll
        for (int ni = 0; ni < 4; ni++) {
            int o = bbase + ni * 8 * LDS_K;
            bh[ni][0] = *(const unsigned*)(sBh + o);
            bh[ni][1] = *(const unsigned*)(sBh + o + 8);
        }
        #pragma unroll
        for (int mi = 0; mi < 4; mi++)
            #pragma unroll
            for (int ni = 0; ni < 4; ni++)
                mma_f16(acc[mi][ni], ah[mi], bh[ni]);
        #pragma unroll
        for (int mi = 0; mi < 4; mi++) {
            int o = abase + mi * 16 * LDS_K;
            al[mi][0] = *(const unsigned*)(sAl + o);
            al[mi][1] = *(const unsigned*)(sAl + o + 8 * LDS_K);
            al[mi][2] = *(const unsigned*)(sAl + o + 8);
            al[mi][3] = *(const unsigned*)(sAl + o + 8 * LDS_K + 8);
        }
        #pragma unroll
        for (int mi = 0; mi < 4; mi++)
            #pragma unroll
            for (int ni = 0; ni < 4; ni++)
                mma_f16(acc[mi][ni], al[mi], bh[ni]);
    }

    #pragma unroll
    for (int mi = 0; mi < 4; mi++) {
        int r0 = bm + warpm * 64 + mi * 16 + g;
        #pragma unroll
        for (int ni = 0; ni < 4; ni++) {
            int col = bn + warpn * 32 + ni * 8 + c * 2;
            float2 bia = *(const float2*)&bias[col];
            float v0 = acc[mi][ni][0] + bia.x;
            float v1 = acc[mi][ni][1] + bia.y;
            float v2 = acc[mi][ni][2] + bia.x;
            float v3 = acc[mi][ni][3] + bia.y;
            size_t o0 = (size_t)r0 * N + col;
            size_t o1 = (size_t)(r0 + 8) * N + col;
            if (EPI == 1) {
                float2 ra = *(const float2*)&R[o0];
                float2 rb = *(const float2*)&R[o1];
                v0 += ra.x; v1 += ra.y; v2 += rb.x; v3 += rb.y;
                *(float2*)&C[o0] = make_float2(v0, v1);
                *(float2*)&C[o1] = make_float2(v2, v3);
            } else {
                if (EPI == 2) {
                    v0 = gelu_exact(v0); v1 = gelu_exact(v1);
                    v2 = gelu_exact(v2); v3 = gelu_exact(v3);
                }
                unsigned h01, l01, h23, l23;
                pack_hilo(v0, v1, h01, l01);
                pack_hilo(v2, v3, h23, l23);
                *(unsigned*)&Chi[o0] = h01; *(unsigned*)&Chi[o1] = h23;
                *(unsigned*)&Clo[o0] = l01; *(unsigned*)&Clo[o1] = l23;
            }
        }
    }
}

// ---------------------------------------------------------------------------
// fp16 2-term flash attention. Q hi/lo; K,V hi only. Fused QKV input.
// smem: Qh 8K | Ql 8K | 2 stages x (Kh 8K + Vh 8K) | fmask 512B
// ---------------------------------------------------------------------------
#define ATT_QH   0
#define ATT_QL   8192
#define ATT_ST   16384
#define ATT_TILE 8192
#define ATT_FM   (ATT_ST + 2*16384)      // 49152
#define ATT_SMEM (ATT_FM + 2*64*4)       // 49664
#define OFF_K    DMODEL
#define OFF_V    (2*DMODEL)

__device__ __forceinline__ unsigned swz(unsigned base, int row, int cc) {
    return base + (unsigned)((row << 7) + (((cc ^ row) & 7) << 4));
}

__global__ __launch_bounds__(128) void attn_mma(
    const __half* __restrict__ QKVh, const __half* __restrict__ QKVl,
    const int* __restrict__ mask,
    __half* __restrict__ Ohi, __half* __restrict__ Olo)
{
    extern __shared__ __align__(16) char sm[];
    const unsigned smb = (unsigned)__cvta_generic_to_shared(sm);
    float* fmask = (float*)(sm + ATT_FM);

    const int b  = blockIdx.z;
    const int h  = blockIdx.y;
    const int qt = blockIdx.x;
    const int tid  = threadIdx.x;
    const int warp = tid >> 5;
    const int lane = tid & 31;
    const int li  = lane & 7;
    const int grp = lane >> 3;
    const int g = lane >> 2;
    const int c = lane & 3;

    const int qrow0 = qt * 64;
    const size_t rowQ = (size_t)(b * SEQ + qrow0);

    {
        #pragma unroll
        for (int i = 0; i < 4; i++) {
            int idx = tid + i * 128;
            int row = idx >> 3, cc = idx & 7;
            size_t gq = (rowQ + row) * QKVN + h * DK + cc * 8;
            cp16(sm + swz(ATT_QH, row, cc), QKVh + gq);
            cp16(sm + swz(ATT_QL, row, cc), QKVl + gq);
        }
        #pragma unroll
        for (int i = 0; i < 4; i++) {
            int idx = tid + i * 128;
            int row = idx >> 3, cc = idx & 7;
            size_t gr = (size_t)(b * SEQ + row) * QKVN + h * DK + cc * 8;
            cp16(sm + swz(ATT_ST, row, cc), QKVh + gr + OFF_K);
            cp16(sm + swz(ATT_ST + ATT_TILE, row, cc), QKVh + gr + OFF_V);
        }
        if (tid < 64) fmask[tid] = (mask[b * SEQ + tid] != 0) ? 0.0f : -1e30f;
        asm volatile("cp.async.commit_group;\n" ::);
    }

    float oacc[8][4];
    #pragma unroll
    for (int nt = 0; nt < 8; nt++)
        #pragma unroll
        for (int r = 0; r < 4; r++) oacc[nt][r] = 0.0f;
    float m0 = -1e30f, m1 = -1e30f, l0 = 0.0f, l1 = 0.0f;
    unsigned qfh[4][4], qfl[4][4];

    const int NT = SEQ / 64;
    for (int kt = 0; kt < NT; kt++) {
        asm volatile("cp.async.wait_group 0;\n" ::);
        __syncthreads();

        if (kt == 0) {
            int qrow = warp * 16 + ((grp & 1) << 3) + li;
            #pragma unroll
            for (int q = 0; q < 4; q++) {
                int cc = 2 * q + (grp >> 1);
                ldsm4(qfh[q][0], qfh[q][1], qfh[q][2], qfh[q][3], smb + swz(ATT_QH, qrow, cc));
                ldsm4(qfl[q][0], qfl[q][1], qfl[q][2], qfl[q][3], smb + swz(ATT_QL, qrow, cc));
            }
        }

        if (kt + 1 < NT) {
            int s = (kt + 1) & 1;
            int kb = (kt + 1) * 64;
            #pragma unroll
            for (int i = 0; i < 4; i++) {
                int idx = tid + i * 128;
                int row = idx >> 3, cc = idx & 7;
                size_t gr = (size_t)(b * SEQ + kb + row) * QKVN + h * DK + cc * 8;
                cp16(sm + swz(ATT_ST + s*16384, row, cc), QKVh + gr + OFF_K);
                cp16(sm + swz(ATT_ST + s*16384 + ATT_TILE, row, cc), QKVh + gr + OFF_V);
            }
            if (tid < 64) fmask[s * 64 + tid] = (mask[b * SEQ + kb + tid] != 0) ? 0.0f : -1e30f;
            asm volatile("cp.async.commit_group;\n" ::);
        }

        const int s = kt & 1;
        const unsigned KHb = ATT_ST + s*16384;
        const unsigned VHb = KHb + ATT_TILE;
        const float* fm = fmask + s * 64;

        float sacc[8][4];
        #pragma unroll
        for (int nt = 0; nt < 8; nt++)
            #pragma unroll
            for (int r = 0; r < 4; r++) sacc[nt][r] = 0.0f;

        {
            const int krow = ((grp >> 1) << 3) + li;
            const int kccb = grp & 1;
            #pragma unroll
            for (int q = 0; q < 4; q++) {
                unsigned kb2[8][2];
                #pragma unroll
                for (int p = 0; p < 4; p++)
                    ldsm4(kb2[2*p][0], kb2[2*p][1], kb2[2*p+1][0], kb2[2*p+1][1],
                          smb + swz(KHb, 16*p + krow, 2*q + kccb));
                #pragma unroll
                for (int nt = 0; nt < 8; nt++) mma_f16(sacc[nt], qfh[q], kb2[nt]);
                #pragma unroll
                for (int nt = 0; nt < 8; nt++) mma_f16(sacc[nt], qfl[q], kb2[nt]);
            }
        }

        float mx0 = -1e30f, mx1 = -1e30f;
        #pragma unroll
        for (int nt = 0; nt < 8; nt++) {
            float f0 = fm[nt*8 + 2*c];
            float f1 = fm[nt*8 + 2*c + 1];
            sacc[nt][0] = fmaf(sacc[nt][0], 0.125f, f0);
            sacc[nt][1] = fmaf(sacc[nt][1], 0.125f, f1);
            sacc[nt][2] = fmaf(sacc[nt][2], 0.125f, f0);
            sacc[nt][3] = fmaf(sacc[nt][3], 0.125f, f1);
            mx0 = fmaxf(mx0, fmaxf(sacc[nt][0], sacc[nt][1]));
            mx1 = fmaxf(mx1, fmaxf(sacc[nt][2], sacc[nt][3]));
        }
        mx0 = fmaxf(mx0, __shfl_xor_sync(0xffffffff, mx0, 1));
        mx0 = fmaxf(mx0, __shfl_xor_sync(0xffffffff, mx0, 2));
        mx1 = fmaxf(mx1, __shfl_xor_sync(0xffffffff, mx1, 1));
        mx1 = fmaxf(mx1, __shfl_xor_sync(0xffffffff, mx1, 2));

        float nm0 = fmaxf(m0, mx0), nm1 = fmaxf(m1, mx1);
        float sc0 = fexp(m0 - nm0), sc1 = fexp(m1 - nm1);
        m0 = nm0; m1 = nm1;
        l0 *= sc0; l1 *= sc1;
        #pragma unroll
        for (int nt = 0; nt < 8; nt++) {
            oacc[nt][0] *= sc0; oacc[nt][1] *= sc0;
            oacc[nt][2] *= sc1; oacc[nt][3] *= sc1;
        }

        float ls0 = 0.0f, ls1 = 0.0f;
        #pragma unroll
        for (int nt = 0; nt < 8; nt++) {
            float p0 = fexp(sacc[nt][0] - nm0);
            float p1 = fexp(sacc[nt][1] - nm0);
            float p2 = fexp(sacc[nt][2] - nm1);
            float p3 = fexp(sacc[nt][3] - nm1);
            sacc[nt][0] = p0; sacc[nt][1] = p1; sacc[nt][2] = p2; sacc[nt][3] = p3;
            ls0 += p0 + p1; ls1 += p2 + p3;
        }
        ls0 += __shfl_xor_sync(0xffffffff, ls0, 1);
        ls0 += __shfl_xor_sync(0xffffffff, ls0, 2);
        ls1 += __shfl_xor_sync(0xffffffff, ls1, 1);
        ls1 += __shfl_xor_sync(0xffffffff, ls1, 2);
        l0 += ls0; l1 += ls1;

        unsigned pfh[4][4], pfl[4][4];
        #pragma unroll
        for (int j = 0; j < 4; j++) {
            pack_hilo(sacc[2*j][0],   sacc[2*j][1],   pfh[j][0], pfl[j][0]);
            pack_hilo(sacc[2*j][2],   sacc[2*j][3],   pfh[j][1], pfl[j][1]);
            pack_hilo(sacc[2*j+1][0], sacc[2*j+1][1], pfh[j][2], pfl[j][2]);
            pack_hilo(sacc[2*j+1][2], sacc[2*j+1][3], pfh[j][3], pfl[j][3]);
        }

        {
            const int vrow = ((grp & 1) << 3) + li;
            const int vccb = grp >> 1;
            #pragma unroll
            for (int j = 0; j < 4; j++) {
                unsigned vb2[8][2];
                #pragma unroll
                for (int d = 0; d < 8; d += 2)
                    ldsm4t(vb2[d][0], vb2[d][1], vb2[d+1][0], vb2[d+1][1],
                           smb + swz(VHb, 16*j + vrow, d + vccb));
                #pragma unroll
                for (int nt = 0; nt < 8; nt++) mma_f16(oacc[nt], pfh[j], vb2[nt]);
                #pragma unroll
                for (int nt = 0; nt < 8; nt++) mma_f16(oacc[nt], pfl[j], vb2[nt]);
            }
        }
    }

    float inv0 = 1.0f / l0, inv1 = 1.0f / l1;
    int r0 = qrow0 + warp * 16 + g;
    int r1 = r0 + 8;
    size_t base0 = (size_t)(b * SEQ + r0) * DMODEL + h * DK;
    size_t base1 = (size_t)(b * SEQ + r1) * DMODEL + h * DK;
    #pragma unroll
    for (int nt = 0; nt < 8; nt++) {
        int col = nt * 8 + 2 * c;
        unsigned hi0, lo0, hi1, lo1;
        pack_hilo(oacc[nt][0] * inv0, oacc[nt][1] * inv0, hi0, lo0);
        pack_hilo(oacc[nt][2] * inv1, oacc[nt][3] * inv1, hi1, lo1);
        *(unsigned*)&Ohi[base0 + col] = hi0;
        *(unsigned*)&Olo[base0 + col] = lo0;
        *(unsigned*)&Ohi[base1 + col] = hi1;
        *(unsigned*)&Olo[base1 + col] = lo1;
    }
}

// ---------------------------------------------------------------------------
// Host launch
// ---------------------------------------------------------------------------
extern "C" void kernel_launch(void* const* d_in, const int* in_sizes, int n_in,
                              void* d_out, int out_size)
{
    const float* x     = (const float*)d_in[0];
    const int*   mask  = (const int*)  d_in[1];
    const float* Wq    = (const float*)d_in[2];
    const float* bq    = (const float*)d_in[3];
    const float* Wk    = (const float*)d_in[4];
    const float* bk    = (const float*)d_in[5];
    const float* Wv    = (const float*)d_in[6];
    const float* bv    = (const float*)d_in[7];
    const float* Wo    = (const float*)d_in[8];
    const float* bo    = (const float*)d_in[9];
    const float* W1    = (const float*)d_in[10];
    const float* b1    = (const float*)d_in[11];
    const float* W2    = (const float*)d_in[12];
    const float* b2    = (const float*)d_in[13];
    const float* ln1_g = (const float*)d_in[14];
    const float* ln1_b = (const float*)d_in[15];
    const float* ln2_g = (const float*)d_in[16];
    const float* ln2_b = (const float*)d_in[17];
    float* out = (float*)d_out;

    float *x1, *bqkv;
    __half *hh, *hl, *qkvh, *qkvl, *ctxh, *ctxl, *h2h, *h2l, *ffnh, *ffnl;
    __half *wqkvh, *woh, *w1h, *w2h;
    cudaGetSymbolAddress((void**)&x1,   g_x1);
    cudaGetSymbolAddress((void**)&bqkv, g_bqkv);
    cudaGetSymbolAddress((void**)&hh,   g_hh);
    cudaGetSymbolAddress((void**)&hl,   g_hl);
    cudaGetSymbolAddress((void**)&qkvh, g_qkvh);
    cudaGetSymbolAddress((void**)&qkvl, g_qkvl);
    cudaGetSymbolAddress((void**)&ctxh, g_ctxh);
    cudaGetSymbolAddress((void**)&ctxl, g_ctxl);
    cudaGetSymbolAddress((void**)&h2h,  g_h2h);
    cudaGetSymbolAddress((void**)&h2l,  g_h2l);
    cudaGetSymbolAddress((void**)&ffnh, g_ffnh);
    cudaGetSymbolAddress((void**)&ffnl, g_ffnl);
    cudaGetSymbolAddress((void**)&wqkvh, g_wqkvh);
    cudaGetSymbolAddress((void**)&woh,  g_woh);
    cudaGetSymbolAddress((void**)&w1h,  g_w1h);
    cudaGetSymbolAddress((void**)&w2h,  g_w2h);

    cudaFuncSetAttribute(attn_mma, cudaFuncAttributeMaxDynamicSharedMemorySize, ATT_SMEM);

    dim3 gW(DMODEL/32, DMODEL/32);

    bias_concat_kernel<<<QKVN/256, 256>>>(bq, bk, bv, bqkv);
    wsplit_kernel<<<gW, 256>>>(Wq, wqkvh,                   DMODEL, DMODEL);
    wsplit_kernel<<<gW, 256>>>(Wk, wqkvh + DMODEL*DMODEL,   DMODEL, DMODEL);
    wsplit_kernel<<<gW, 256>>>(Wv, wqkvh + 2*DMODEL*DMODEL, DMODEL, DMODEL);
    ln_kernel<<<MROWS, 256>>>(x, ln1_g, ln1_b, hh, hl);

    // fused QKV projection
    dim3 gQKV(QKVN/128, MROWS/128);
    mma_gemm<3><<<gQKV, 256>>>(hh, hl, wqkvh, bqkv, nullptr, nullptr,
                               qkvh, qkvl, MROWS, QKVN, DMODEL);

    wsplit_kernel<<<gW, 256>>>(Wo, woh, DMODEL, DMODEL);
    dim3 gW1(DFF/32, DMODEL/32);
    wsplit_kernel<<<gW1, 256>>>(W1, w1h, DMODEL, DFF);
    dim3 gW2(DMODEL/32, DFF/32);
    wsplit_kernel<<<gW2, 256>>>(W2, w2h, DFF, DMODEL);

    // attention -> ctx fp16 hi/lo
    dim3 gA(SEQ/64, NHEADS, BATCH);
    attn_mma<<<gA, 128, ATT_SMEM>>>(qkvh, qkvl, mask, ctxh, ctxl);

    // output projection + residual -> x1 (fp32)
    dim3 gP(DMODEL/128, MROWS/128);
    mma_gemm<1><<<gP, 256>>>(ctxh, ctxl, woh, bo, x, x1, nullptr, nullptr, MROWS, DMODEL, DMODEL);

    // LN2 -> fp16 split
    ln_kernel<<<MROWS, 256>>>(x1, ln2_g, ln2_b, h2h, h2l);

    // FFN up + GELU -> ffn fp16 hi/lo
    dim3 gF1(DFF/128, MROWS/128);
    mma_gemm<2><<<gF1, 256>>>(h2h, h2l, w1h, b1, nullptr, nullptr, ffnh, ffnl, MROWS, DFF, DMODEL);

    // FFN down + residual -> out (fp32)
    dim3 gF2(DMODEL/128, MROWS/128);
    mma_gemm<1><<<gF2, 256>>>(ffnh, ffnl, w2h, b2, x1, out, nullptr, nullptr, MROWS, DMODEL, DFF);
}

// round 11
// speedup vs baseline: 3.1065x; 1.5915x over previous
#include <cuda_runtime.h>
#include <cuda_fp16.h>
#include <math.h>

// ---------------------------------------------------------------------------
// TransformerEncoderBlock: B=4, S=2048, D=1024, H=16, Dk=64, Dff=4096, fp32.
// Round 11: full single-term fp16 (activations AND weights hi-only).
// GEMM: 16 MMAs/warp/k-tile, 2 smem tiles/stage. Attention: 1 MMA per stage.
// Pure deletion from R10 (measured 2250us, rel_err 1.65e-4).
// Expected rel_err ~2.5e-4 (A+B side fp16 rounding in quadrature).
// ---------------------------------------------------------------------------

#define BATCH   4
#define SEQ     2048
#define DMODEL  1024
#define NHEADS  16
#define DK      64
#define DFF     4096
#define MROWS   (BATCH * SEQ)   // 8192
#define QKVN    3072            // fused QKV width

#define LDS_K   24              // GEMM smem pad (R4)

// ---------------- scratch (__device__ globals; no allocs allowed) ----------
__device__ float g_x1[MROWS * DMODEL];
__device__ float g_bqkv[QKVN];

__device__ __align__(16) __half g_hh  [MROWS * DMODEL];
__device__ __align__(16) __half g_qkvh[MROWS * QKVN];
__device__ __align__(16) __half g_ctxh[MROWS * DMODEL];
__device__ __align__(16) __half g_h2h [MROWS * DMODEL];
__device__ __align__(16) __half g_ffnh[MROWS * DFF];

__device__ __align__(16) __half g_wqkvh[QKVN*DMODEL];
__device__ __align__(16) __half g_woh[DMODEL*DMODEL];
__device__ __align__(16) __half g_w1h[DFF*DMODEL];
__device__ __align__(16) __half g_w2h[DMODEL*DFF];

// ---------------------------------------------------------------------------
__device__ __forceinline__ float gelu_exact(float x) {
    return 0.5f * x * (1.0f + erff(x * 0.70710678118654752f));
}
__device__ __forceinline__ void cp16(const void* dst_smem, const void* src) {
    unsigned s = (unsigned)__cvta_generic_to_shared(dst_smem);
    asm volatile("cp.async.cg.shared.global [%0], [%1], 16;\n" :: "r"(s), "l"(src));
}
__device__ __forceinline__ void mma_f16(float* c, const unsigned* a, const unsigned* b) {
    asm volatile(
        "mma.sync.aligned.m16n8k16.row.col.f32.f16.f16.f32 "
        "{%0,%1,%2,%3}, {%4,%5,%6,%7}, {%8,%9}, {%0,%1,%2,%3};\n"
        : "+f"(c[0]), "+f"(c[1]), "+f"(c[2]), "+f"(c[3])
        : "r"(a[0]), "r"(a[1]), "r"(a[2]), "r"(a[3]), "r"(b[0]), "r"(b[1]));
}
__device__ __forceinline__ void ldsm4(unsigned& r0, unsigned& r1, unsigned& r2, unsigned& r3, unsigned addr) {
    asm volatile("ldmatrix.sync.aligned.m8n8.x4.shared.b16 {%0,%1,%2,%3}, [%4];"
                 : "=r"(r0), "=r"(r1), "=r"(r2), "=r"(r3) : "r"(addr));
}
__device__ __forceinline__ void ldsm4t(unsigned& r0, unsigned& r1, unsigned& r2, unsigned& r3, unsigned addr) {
    asm volatile("ldmatrix.sync.aligned.m8n8.x4.trans.shared.b16 {%0,%1,%2,%3}, [%4];"
                 : "=r"(r0), "=r"(r1), "=r"(r2), "=r"(r3) : "r"(addr));
}
// FFMA-only e^x for x <= 0 (clamped). rel err ~4e-5.
__device__ __forceinline__ float fexp(float x) {
    x = fmaxf(x, -60.0f);
    float t = x * 1.4426950408889634f;
    float z = t + 12582912.0f;
    int   e = __float_as_int(z) - 0x4B400000;
    float f = t - (z - 12582912.0f);
    float p = 0.0096181291f;
    p = fmaf(p, f, 0.0555041087f);
    p = fmaf(p, f, 0.2402265070f);
    p = fmaf(p, f, 0.6931471806f);
    p = fmaf(p, f, 1.0f);
    return __int_as_float(__float_as_int(p) + (e << 23));
}
__device__ __forceinline__ unsigned pack_f16(float a, float b) {
    __half2 h2 = __floats2half2_rn(a, b);
    return *(unsigned*)&h2;
}

// ---------------------------------------------------------------------------
// bias concat: [bq | bk | bv] -> g_bqkv
// ---------------------------------------------------------------------------
__global__ __launch_bounds__(256) void bias_concat_kernel(
    const float* __restrict__ a, const float* __restrict__ b,
    const float* __restrict__ c, float* __restrict__ o)
{
    int i = blockIdx.x * 256 + threadIdx.x;
    float v = (i < DMODEL) ? a[i] : (i < 2*DMODEL) ? b[i - DMODEL] : c[i - 2*DMODEL];
    o[i] = v;
}

// ---------------------------------------------------------------------------
// Weight convert + transpose:  W[K][N] fp32  ->  Th[N][K] fp16
// ---------------------------------------------------------------------------
__global__ __launch_bounds__(256) void wsplit_kernel(
    const float* __restrict__ W, __half* __restrict__ Th, int K, int N)
{
    __shared__ float tile[32][33];
    int n0 = blockIdx.x * 32, k0 = blockIdx.y * 32;
    int tx = threadIdx.x & 31;
    int ty = threadIdx.x >> 5;
    #pragma unroll
    for (int i = 0; i < 32; i += 8)
        tile[ty + i][tx] = W[(size_t)(k0 + ty + i) * N + n0 + tx];
    __syncthreads();
    #pragma unroll
    for (int i = 0; i < 32; i += 8) {
        float v = tile[tx][ty + i];
        Th[(size_t)(n0 + ty + i) * K + k0 + tx] = __float2half_rn(v);
    }
}

// ---------------------------------------------------------------------------
// LayerNorm -> fp16 output.
// ---------------------------------------------------------------------------
__global__ __launch_bounds__(256) void ln_kernel(
    const float* __restrict__ x, const float* __restrict__ gamma,
    const float* __restrict__ beta, __half* __restrict__ out_hi)
{
    int row = blockIdx.x;
    int tid = threadIdx.x;
    const float4* xr = (const float4*)(x + (size_t)row * DMODEL);
    float4 v = xr[tid];

    __shared__ float red[256];
    red[tid] = v.x + v.y + v.z + v.w; __syncthreads();
    #pragma unroll
    for (int off = 128; off > 0; off >>= 1) {
        if (tid < off) red[tid] += red[tid + off];
        __syncthreads();
    }
    float mu = red[0] * (1.0f / DMODEL);
    __syncthreads();

    float dx0 = v.x - mu, dx1 = v.y - mu, dx2 = v.z - mu, dx3 = v.w - mu;
    red[tid] = dx0*dx0 + dx1*dx1 + dx2*dx2 + dx3*dx3; __syncthreads();
    #pragma unroll
    for (int off = 128; off > 0; off >>= 1) {
        if (tid < off) red[tid] += red[tid + off];
        __syncthreads();
    }
    float rs = rsqrtf(red[0] * (1.0f / DMODEL) + 1e-5f);

    float4 g4 = ((const float4*)gamma)[tid];
    float4 b4 = ((const float4*)beta)[tid];
    float o0 = dx0 * rs * g4.x + b4.x;
    float o1 = dx1 * rs * g4.y + b4.y;
    float o2 = dx2 * rs * g4.z + b4.z;
    float o3 = dx3 * rs * g4.w + b4.w;

    size_t o = (size_t)row * DMODEL + tid * 4;
    *(unsigned*)&out_hi[o]   = pack_f16(o0, o1);
    *(unsigned*)&out_hi[o+2] = pack_f16(o2, o3);
}

// ---------------------------------------------------------------------------
// fp16 MMA GEMM: C = Ah[M,K] @ Bh^T[N,K] + bias (+R | gelu)
// CTA 128x128xBK16, 8 warps (2x4), warp tile 64x32, m16n8k16 mma.
// R4 loop body, single A term, 2 smem tiles per stage.
// EPI: 1 bias+R->f32 | 2 bias+gelu->fp16 | 3 bias->fp16
// ---------------------------------------------------------------------------
template<int EPI>
__global__ __launch_bounds__(256) void mma_gemm(
    const __half* __restrict__ Ah, const __half* __restrict__ Bh,
    const float* __restrict__ bias, const float* __restrict__ R,
    float* __restrict__ C, __half* __restrict__ Chi, int M, int N, int K)
{
    __shared__ __align__(16) __half smem[2][2][128 * LDS_K];

    const int tid = threadIdx.x;
    const int bm = blockIdx.y * 128;
    const int bn = blockIdx.x * 128;

    const int lrow  = tid >> 1;
    const int lhalf = tid & 1;
    const __half* src0 = Ah + (size_t)(bm + lrow) * K + lhalf * 8;
    const __half* src2 = Bh + (size_t)(bn + lrow) * K + lhalf * 8;
    const int sdst = lrow * LDS_K + lhalf * 8;

    const int warp  = tid >> 5;
    const int lane  = tid & 31;
    const int warpm = warp >> 2;
    const int warpn = warp & 3;
    const int g = lane >> 2;
    const int c = lane & 3;

    float acc[4][4][4];
    #pragma unroll
    for (int i = 0; i < 4; i++)
        #pragma unroll
        for (int j = 0; j < 4; j++)
            #pragma unroll
            for (int r = 0; r < 4; r++) acc[i][j][r] = 0.0f;

    const int nk = K >> 4;

    cp16(&smem[0][0][sdst], src0);
    cp16(&smem[0][1][sdst], src2);
    asm volatile("cp.async.commit_group;\n" ::);

    for (int t = 0; t < nk; t++) {
        asm volatile("cp.async.wait_group 0;\n" ::);
        __syncthreads();
        if (t + 1 < nk) {
            int ko = (t + 1) << 4;
            int s = (t + 1) & 1;
            cp16(&smem[s][0][sdst], src0 + ko);
            cp16(&smem[s][1][sdst], src2 + ko);
            asm volatile("cp.async.commit_group;\n" ::);
        }

        const __half* sAh = smem[t & 1][0];
        const __half* sBh = smem[t & 1][1];

        unsigned ah[4][4], bh[4][2];
        const int abase = (warpm * 64 + g) * LDS_K + c * 2;
        const int bbase = (warpn * 32 + g) * LDS_K + c * 2;

        #pragma unroll
        for (int mi = 0; mi < 4; mi++) {
            int o = abase + mi * 16 * LDS_K;
            ah[mi][0] = *(const unsigned*)(sAh + o);
            ah[mi][1] = *(const unsigned*)(sAh + o + 8 * LDS_K);
            ah[mi][2] = *(const unsigned*)(sAh + o + 8);
            ah[mi][3] = *(const unsigned*)(sAh + o + 8 * LDS_K + 8);
        }
        #pragma unroll
        for (int ni = 0; ni < 4; ni++) {
            int o = bbase + ni * 8 * LDS_K;
            bh[ni][0] = *(const unsigned*)(sBh + o);
            bh[ni][1] = *(const unsigned*)(sBh + o + 8);
        }
        #pragma unroll
        for (int mi = 0; mi < 4; mi++)
            #pragma unroll
            for (int ni = 0; ni < 4; ni++)
                mma_f16(acc[mi][ni], ah[mi], bh[ni]);
    }

    #pragma unroll
    for (int mi = 0; mi < 4; mi++) {
        int r0 = bm + warpm * 64 + mi * 16 + g;
        #pragma unroll
        for (int ni = 0; ni < 4; ni++) {
            int col = bn + warpn * 32 + ni * 8 + c * 2;
            float2 bia = *(const float2*)&bias[col];
            float v0 = acc[mi][ni][0] + bia.x;
            float v1 = acc[mi][ni][1] + bia.y;
            float v2 = acc[mi][ni][2] + bia.x;
            float v3 = acc[mi][ni][3] + bia.y;
            size_t o0 = (size_t)r0 * N + col;
            size_t o1 = (size_t)(r0 + 8) * N + col;
            if (EPI == 1) {
                float2 ra = *(const float2*)&R[o0];
                float2 rb = *(const float2*)&R[o1];
                v0 += ra.x; v1 += ra.y; v2 += rb.x; v3 += rb.y;
                *(float2*)&C[o0] = make_float2(v0, v1);
                *(float2*)&C[o1] = make_float2(v2, v3);
            } else {
                if (EPI == 2) {
                    v0 = gelu_exact(v0); v1 = gelu_exact(v1);
                    v2 = gelu_exact(v2); v3 = gelu_exact(v3);
                }
                *(unsigned*)&Chi[o0] = pack_f16(v0, v1);
                *(unsigned*)&Chi[o1] = pack_f16(v2, v3);
            }
        }
    }
}

// ---------------------------------------------------------------------------
// fp16 flash attention, single term. Fused QKV input (stride 3072).
// smem: Qh 8K | 2 stages x (Kh 8K + Vh 8K) | fmask 512B
// ---------------------------------------------------------------------------
#define ATT_QH   0
#define ATT_ST   8192
#define ATT_TILE 8192
#define ATT_FM   (ATT_ST + 2*16384)      // 40960
#define ATT_SMEM (ATT_FM + 2*64*4)       // 41472
#define OFF_K    DMODEL
#define OFF_V    (2*DMODEL)

__device__ __forceinline__ unsigned swz(unsigned base, int row, int cc) {
    return base + (unsigned)((row << 7) + (((cc ^ row) & 7) << 4));
}

__global__ __launch_bounds__(128) void attn_mma(
    const __half* __restrict__ QKVh, const int* __restrict__ mask,
    __half* __restrict__ Ohi)
{
    extern __shared__ __align__(16) char sm[];
    const unsigned smb = (unsigned)__cvta_generic_to_shared(sm);
    float* fmask = (float*)(sm + ATT_FM);

    const int b  = blockIdx.z;
    const int h  = blockIdx.y;
    const int qt = blockIdx.x;
    const int tid  = threadIdx.x;
    const int warp = tid >> 5;
    const int lane = tid & 31;
    const int li  = lane & 7;
    const int grp = lane >> 3;
    const int g = lane >> 2;
    const int c = lane & 3;

    const int qrow0 = qt * 64;
    const size_t rowQ = (size_t)(b * SEQ + qrow0);

    {
        #pragma unroll
        for (int i = 0; i < 4; i++) {
            int idx = tid + i * 128;
            int row = idx >> 3, cc = idx & 7;
            size_t gq = (rowQ + row) * QKVN + h * DK + cc * 8;
            cp16(sm + swz(ATT_QH, row, cc), QKVh + gq);
        }
        #pragma unroll
        for (int i = 0; i < 4; i++) {
            int idx = tid + i * 128;
            int row = idx >> 3, cc = idx & 7;
            size_t gr = (size_t)(b * SEQ + row) * QKVN + h * DK + cc * 8;
            cp16(sm + swz(ATT_ST, row, cc), QKVh + gr + OFF_K);
            cp16(sm + swz(ATT_ST + ATT_TILE, row, cc), QKVh + gr + OFF_V);
        }
        if (tid < 64) fmask[tid] = (mask[b * SEQ + tid] != 0) ? 0.0f : -1e30f;
        asm volatile("cp.async.commit_group;\n" ::);
    }

    float oacc[8][4];
    #pragma unroll
    for (int nt = 0; nt < 8; nt++)
        #pragma unroll
        for (int r = 0; r < 4; r++) oacc[nt][r] = 0.0f;
    float m0 = -1e30f, m1 = -1e30f, l0 = 0.0f, l1 = 0.0f;
    unsigned qfh[4][4];

    const int NT = SEQ / 64;
    for (int kt = 0; kt < NT; kt++) {
        asm volatile("cp.async.wait_group 0;\n" ::);
        __syncthreads();

        if (kt == 0) {
            int qrow = warp * 16 + ((grp & 1) << 3) + li;
            #pragma unroll
            for (int q = 0; q < 4; q++) {
                int cc = 2 * q + (grp >> 1);
                ldsm4(qfh[q][0], qfh[q][1], qfh[q][2], qfh[q][3], smb + swz(ATT_QH, qrow, cc));
            }
        }

        if (kt + 1 < NT) {
            int s = (kt + 1) & 1;
            int kb = (kt + 1) * 64;
            #pragma unroll
            for (int i = 0; i < 4; i++) {
                int idx = tid + i * 128;
                int row = idx >> 3, cc = idx & 7;
                size_t gr = (size_t)(b * SEQ + kb + row) * QKVN + h * DK + cc * 8;
                cp16(sm + swz(ATT_ST + s*16384, row, cc), QKVh + gr + OFF_K);
                cp16(sm + swz(ATT_ST + s*16384 + ATT_TILE, row, cc), QKVh + gr + OFF_V);
            }
            if (tid < 64) fmask[s * 64 + tid] = (mask[b * SEQ + kb + tid] != 0) ? 0.0f : -1e30f;
            asm volatile("cp.async.commit_group;\n" ::);
        }

        const int s = kt & 1;
        const unsigned KHb = ATT_ST + s*16384;
        const unsigned VHb = KHb + ATT_TILE;
        const float* fm = fmask + s * 64;

        float sacc[8][4];
        #pragma unroll
        for (int nt = 0; nt < 8; nt++)
            #pragma unroll
            for (int r = 0; r < 4; r++) sacc[nt][r] = 0.0f;

        {
            const int krow = ((grp >> 1) << 3) + li;
            const int kccb = grp & 1;
            #pragma unroll
            for (int q = 0; q < 4; q++) {
                unsigned kb2[8][2];
                #pragma unroll
                for (int p = 0; p < 4; p++)
                    ldsm4(kb2[2*p][0], kb2[2*p][1], kb2[2*p+1][0], kb2[2*p+1][1],
                          smb + swz(KHb, 16*p + krow, 2*q + kccb));
                #pragma unroll
                for (int nt = 0; nt < 8; nt++) mma_f16(sacc[nt], qfh[q], kb2[nt]);
            }
        }

        float mx0 = -1e30f, mx1 = -1e30f;
        #pragma unroll
        for (int nt = 0; nt < 8; nt++) {
            float f0 = fm[nt*8 + 2*c];
            float f1 = fm[nt*8 + 2*c + 1];
            sacc[nt][0] = fmaf(sacc[nt][0], 0.125f, f0);
            sacc[nt][1] = fmaf(sacc[nt][1], 0.125f, f1);
            sacc[nt][2] = fmaf(sacc[nt][2], 0.125f, f0);
            sacc[nt][3] = fmaf(sacc[nt][3], 0.125f, f1);
            mx0 = fmaxf(mx0, fmaxf(sacc[nt][0], sacc[nt][1]));
            mx1 = fmaxf(mx1, fmaxf(sacc[nt][2], sacc[nt][3]));
        }
        mx0 = fmaxf(mx0, __shfl_xor_sync(0xffffffff, mx0, 1));
        mx0 = fmaxf(mx0, __shfl_xor_sync(0xffffffff, mx0, 2));
        mx1 = fmaxf(mx1, __shfl_xor_sync(0xffffffff, mx1, 1));
        mx1 = fmaxf(mx1, __shfl_xor_sync(0xffffffff, mx1, 2));

        float nm0 = fmaxf(m0, mx0), nm1 = fmaxf(m1, mx1);
        float sc0 = fexp(m0 - nm0), sc1 = fexp(m1 - nm1);
        m0 = nm0; m1 = nm1;
        l0 *= sc0; l1 *= sc1;
        #pragma unroll
        for (int nt = 0; nt < 8; nt++) {
            oacc[nt][0] *= sc0; oacc[nt][1] *= sc0;
            oacc[nt][2] *= sc1; oacc[nt][3] *= sc1;
        }

        float ls0 = 0.0f, ls1 = 0.0f;
        #pragma unroll
        for (int nt = 0; nt < 8; nt++) {
            float p0 = fexp(sacc[nt][0] - nm0);
            float p1 = fexp(sacc[nt][1] - nm0);
            float p2 = fexp(sacc[nt][2] - nm1);
            float p3 = fexp(sacc[nt][3] - nm1);
            sacc[nt][0] = p0; sacc[nt][1] = p1; sacc[nt][2] = p2; sacc[nt][3] = p3;
            ls0 += p0 + p1; ls1 += p2 + p3;
        }
        ls0 += __shfl_xor_sync(0xffffffff, ls0, 1);
        ls0 += __shfl_xor_sync(0xffffffff, ls0, 2);
        ls1 += __shfl_xor_sync(0xffffffff, ls1, 1);
        ls1 += __shfl_xor_sync(0xffffffff, ls1, 2);
        l0 += ls0; l1 += ls1;

        unsigned pfh[4][4];
        #pragma unroll
        for (int j = 0; j < 4; j++) {
            pfh[j][0] = pack_f16(sacc[2*j][0],   sacc[2*j][1]);
            pfh[j][1] = pack_f16(sacc[2*j][2],   sacc[2*j][3]);
            pfh[j][2] = pack_f16(sacc[2*j+1][0], sacc[2*j+1][1]);
            pfh[j][3] = pack_f16(sacc[2*j+1][2], sacc[2*j+1][3]);
        }

        {
            const int vrow = ((grp & 1) << 3) + li;
            const int vccb = grp >> 1;
            #pragma unroll
            for (int j = 0; j < 4; j++) {
                unsigned vb2[8][2];
                #pragma unroll
                for (int d = 0; d < 8; d += 2)
                    ldsm4t(vb2[d][0], vb2[d][1], vb2[d+1][0], vb2[d+1][1],
                           smb + swz(VHb, 16*j + vrow, d + vccb));
                #pragma unroll
                for (int nt = 0; nt < 8; nt++) mma_f16(oacc[nt], pfh[j], vb2[nt]);
            }
        }
    }

    float inv0 = 1.0f / l0, inv1 = 1.0f / l1;
    int r0 = qrow0 + warp * 16 + g;
    int r1 = r0 + 8;
    size_t base0 = (size_t)(b * SEQ + r0) * DMODEL + h * DK;
    size_t base1 = (size_t)(b * SEQ + r1) * DMODEL + h * DK;
    #pragma unroll
    for (int nt = 0; nt < 8; nt++) {
        int col = nt * 8 + 2 * c;
        *(unsigned*)&Ohi[base0 + col] = pack_f16(oacc[nt][0] * inv0, oacc[nt][1] * inv0);
        *(unsigned*)&Ohi[base1 + col] = pack_f16(oacc[nt][2] * inv1, oacc[nt][3] * inv1);
    }
}

// ---------------------------------------------------------------------------
// Host launch
// ---------------------------------------------------------------------------
extern "C" void kernel_launch(void* const* d_in, const int* in_sizes, int n_in,
                              void* d_out, int out_size)
{
    const float* x     = (const float*)d_in[0];
    const int*   mask  = (const int*)  d_in[1];
    const float* Wq    = (const float*)d_in[2];
    const float* bq    = (const float*)d_in[3];
    const float* Wk    = (const float*)d_in[4];
    const float* bk    = (const float*)d_in[5];
    const float* Wv    = (const float*)d_in[6];
    const float* bv    = (const float*)d_in[7];
    const float* Wo    = (const float*)d_in[8];
    const float* bo    = (const float*)d_in[9];
    const float* W1    = (const float*)d_in[10];
    const float* b1    = (const float*)d_in[11];
    const float* W2    = (const float*)d_in[12];
    const float* b2    = (const float*)d_in[13];
    const float* ln1_g = (const float*)d_in[14];
    const float* ln1_b = (const float*)d_in[15];
    const float* ln2_g = (const float*)d_in[16];
    const float* ln2_b = (const float*)d_in[17];
    float* out = (float*)d_out;

    float *x1, *bqkv;
    __half *hh, *qkvh, *ctxh, *h2h, *ffnh;
    __half *wqkvh, *woh, *w1h, *w2h;
    cudaGetSymbolAddress((void**)&x1,   g_x1);
    cudaGetSymbolAddress((void**)&bqkv, g_bqkv);
    cudaGetSymbolAddress((void**)&hh,   g_hh);
    cudaGetSymbolAddress((void**)&qkvh, g_qkvh);
    cudaGetSymbolAddress((void**)&ctxh, g_ctxh);
    cudaGetSymbolAddress((void**)&h2h,  g_h2h);
    cudaGetSymbolAddress((void**)&ffnh, g_ffnh);
    cudaGetSymbolAddress((void**)&wqkvh, g_wqkvh);
    cudaGetSymbolAddress((void**)&woh,  g_woh);
    cudaGetSymbolAddress((void**)&w1h,  g_w1h);
    cudaGetSymbolAddress((void**)&w2h,  g_w2h);

    cudaFuncSetAttribute(attn_mma, cudaFuncAttributeMaxDynamicSharedMemorySize, ATT_SMEM);

    dim3 gW(DMODEL/32, DMODEL/32);

    bias_concat_kernel<<<QKVN/256, 256>>>(bq, bk, bv, bqkv);
    wsplit_kernel<<<gW, 256>>>(Wq, wqkvh,                   DMODEL, DMODEL);
    wsplit_kernel<<<gW, 256>>>(Wk, wqkvh + DMODEL*DMODEL,   DMODEL, DMODEL);
    wsplit_kernel<<<gW, 256>>>(Wv, wqkvh + 2*DMODEL*DMODEL, DMODEL, DMODEL);
    ln_kernel<<<MROWS, 256>>>(x, ln1_g, ln1_b, hh);

    // fused QKV projection
    dim3 gQKV(QKVN/128, MROWS/128);
    mma_gemm<3><<<gQKV, 256>>>(hh, wqkvh, bqkv, nullptr, nullptr, qkvh, MROWS, QKVN, DMODEL);

    wsplit_kernel<<<gW, 256>>>(Wo, woh, DMODEL, DMODEL);
    dim3 gW1(DFF/32, DMODEL/32);
    wsplit_kernel<<<gW1, 256>>>(W1, w1h, DMODEL, DFF);
    dim3 gW2(DMODEL/32, DFF/32);
    wsplit_kernel<<<gW2, 256>>>(W2, w2h, DFF, DMODEL);

    // attention -> ctx fp16
    dim3 gA(SEQ/64, NHEADS, BATCH);
    attn_mma<<<gA, 128, ATT_SMEM>>>(qkvh, mask, ctxh);

    // output projection + residual -> x1 (fp32)
    dim3 gP(DMODEL/128, MROWS/128);
    mma_gemm<1><<<gP, 256>>>(ctxh, woh, bo, x, x1, nullptr, MROWS, DMODEL, DMODEL);

    // LN2 -> fp16
    ln_kernel<<<MROWS, 256>>>(x1, ln2_g, ln2_b, h2h);

    // FFN up + GELU -> fp16
    dim3 gF1(DFF/128, MROWS/128);
    mma_gemm<2><<<gF1, 256>>>(h2h, w1h, b1, nullptr, nullptr, ffnh, MROWS, DFF, DMODEL);

    // FFN down + residual -> out (fp32)
    dim3 gF2(DMODEL/128, MROWS/128);
    mma_gemm<1><<<gF2, 256>>>(ffnh, w2h, b2, x1, out, nullptr, MROWS, DMODEL, DFF);
}

// round 12
// speedup vs baseline: 3.1987x; 1.0297x over previous
#include <cuda_runtime.h>
#include <cuda_fp16.h>
#include <math.h>

// ---------------------------------------------------------------------------
// TransformerEncoderBlock: B=4, S=2048, D=1024, H=16, Dk=64, Dff=4096, fp32.
// Round 12: R11 (fp16 single-term, 1414us) + 3-stage cp.async pipeline in the
// GEMM (staging only; fragment code / registers / loop body unchanged).
// ---------------------------------------------------------------------------

#define BATCH   4
#define SEQ     2048
#define DMODEL  1024
#define NHEADS  16
#define DK      64
#define DFF     4096
#define MROWS   (BATCH * SEQ)   // 8192
#define QKVN    3072            // fused QKV width

#define LDS_K   24              // GEMM smem pad

// ---------------- scratch (__device__ globals; no allocs allowed) ----------
__device__ float g_x1[MROWS * DMODEL];
__device__ float g_bqkv[QKVN];

__device__ __align__(16) __half g_hh  [MROWS * DMODEL];
__device__ __align__(16) __half g_qkvh[MROWS * QKVN];
__device__ __align__(16) __half g_ctxh[MROWS * DMODEL];
__device__ __align__(16) __half g_h2h [MROWS * DMODEL];
__device__ __align__(16) __half g_ffnh[MROWS * DFF];

__device__ __align__(16) __half g_wqkvh[QKVN*DMODEL];
__device__ __align__(16) __half g_woh[DMODEL*DMODEL];
__device__ __align__(16) __half g_w1h[DFF*DMODEL];
__device__ __align__(16) __half g_w2h[DMODEL*DFF];

// ---------------------------------------------------------------------------
__device__ __forceinline__ float gelu_exact(float x) {
    return 0.5f * x * (1.0f + erff(x * 0.70710678118654752f));
}
__device__ __forceinline__ void cp16(const void* dst_smem, const void* src) {
    unsigned s = (unsigned)__cvta_generic_to_shared(dst_smem);
    asm volatile("cp.async.cg.shared.global [%0], [%1], 16;\n" :: "r"(s), "l"(src));
}
__device__ __forceinline__ void mma_f16(float* c, const unsigned* a, const unsigned* b) {
    asm volatile(
        "mma.sync.aligned.m16n8k16.row.col.f32.f16.f16.f32 "
        "{%0,%1,%2,%3}, {%4,%5,%6,%7}, {%8,%9}, {%0,%1,%2,%3};\n"
        : "+f"(c[0]), "+f"(c[1]), "+f"(c[2]), "+f"(c[3])
        : "r"(a[0]), "r"(a[1]), "r"(a[2]), "r"(a[3]), "r"(b[0]), "r"(b[1]));
}
__device__ __forceinline__ void ldsm4(unsigned& r0, unsigned& r1, unsigned& r2, unsigned& r3, unsigned addr) {
    asm volatile("ldmatrix.sync.aligned.m8n8.x4.shared.b16 {%0,%1,%2,%3}, [%4];"
                 : "=r"(r0), "=r"(r1), "=r"(r2), "=r"(r3) : "r"(addr));
}
__device__ __forceinline__ void ldsm4t(unsigned& r0, unsigned& r1, unsigned& r2, unsigned& r3, unsigned addr) {
    asm volatile("ldmatrix.sync.aligned.m8n8.x4.trans.shared.b16 {%0,%1,%2,%3}, [%4];"
                 : "=r"(r0), "=r"(r1), "=r"(r2), "=r"(r3) : "r"(addr));
}
// FFMA-only e^x for x <= 0 (clamped). rel err ~4e-5.
__device__ __forceinline__ float fexp(float x) {
    x = fmaxf(x, -60.0f);
    float t = x * 1.4426950408889634f;
    float z = t + 12582912.0f;
    int   e = __float_as_int(z) - 0x4B400000;
    float f = t - (z - 12582912.0f);
    float p = 0.0096181291f;
    p = fmaf(p, f, 0.0555041087f);
    p = fmaf(p, f, 0.2402265070f);
    p = fmaf(p, f, 0.6931471806f);
    p = fmaf(p, f, 1.0f);
    return __int_as_float(__float_as_int(p) + (e << 23));
}
__device__ __forceinline__ unsigned pack_f16(float a, float b) {
    __half2 h2 = __floats2half2_rn(a, b);
    return *(unsigned*)&h2;
}

// ---------------------------------------------------------------------------
// bias concat: [bq | bk | bv] -> g_bqkv
// ---------------------------------------------------------------------------
__global__ __launch_bounds__(256) void bias_concat_kernel(
    const float* __restrict__ a, const float* __restrict__ b,
    const float* __restrict__ c, float* __restrict__ o)
{
    int i = blockIdx.x * 256 + threadIdx.x;
    float v = (i < DMODEL) ? a[i] : (i < 2*DMODEL) ? b[i - DMODEL] : c[i - 2*DMODEL];
    o[i] = v;
}

// ---------------------------------------------------------------------------
// Weight convert + transpose:  W[K][N] fp32  ->  Th[N][K] fp16
// ---------------------------------------------------------------------------
__global__ __launch_bounds__(256) void wsplit_kernel(
    const float* __restrict__ W, __half* __restrict__ Th, int K, int N)
{
    __shared__ float tile[32][33];
    int n0 = blockIdx.x * 32, k0 = blockIdx.y * 32;
    int tx = threadIdx.x & 31;
    int ty = threadIdx.x >> 5;
    #pragma unroll
    for (int i = 0; i < 32; i += 8)
        tile[ty + i][tx] = W[(size_t)(k0 + ty + i) * N + n0 + tx];
    __syncthreads();
    #pragma unroll
    for (int i = 0; i < 32; i += 8) {
        float v = tile[tx][ty + i];
        Th[(size_t)(n0 + ty + i) * K + k0 + tx] = __float2half_rn(v);
    }
}

// ---------------------------------------------------------------------------
// LayerNorm -> fp16 output.
// ---------------------------------------------------------------------------
__global__ __launch_bounds__(256) void ln_kernel(
    const float* __restrict__ x, const float* __restrict__ gamma,
    const float* __restrict__ beta, __half* __restrict__ out_hi)
{
    int row = blockIdx.x;
    int tid = threadIdx.x;
    const float4* xr = (const float4*)(x + (size_t)row * DMODEL);
    float4 v = xr[tid];

    __shared__ float red[256];
    red[tid] = v.x + v.y + v.z + v.w; __syncthreads();
    #pragma unroll
    for (int off = 128; off > 0; off >>= 1) {
        if (tid < off) red[tid] += red[tid + off];
        __syncthreads();
    }
    float mu = red[0] * (1.0f / DMODEL);
    __syncthreads();

    float dx0 = v.x - mu, dx1 = v.y - mu, dx2 = v.z - mu, dx3 = v.w - mu;
    red[tid] = dx0*dx0 + dx1*dx1 + dx2*dx2 + dx3*dx3; __syncthreads();
    #pragma unroll
    for (int off = 128; off > 0; off >>= 1) {
        if (tid < off) red[tid] += red[tid + off];
        __syncthreads();
    }
    float rs = rsqrtf(red[0] * (1.0f / DMODEL) + 1e-5f);

    float4 g4 = ((const float4*)gamma)[tid];
    float4 b4 = ((const float4*)beta)[tid];
    float o0 = dx0 * rs * g4.x + b4.x;
    float o1 = dx1 * rs * g4.y + b4.y;
    float o2 = dx2 * rs * g4.z + b4.z;
    float o3 = dx3 * rs * g4.w + b4.w;

    size_t o = (size_t)row * DMODEL + tid * 4;
    *(unsigned*)&out_hi[o]   = pack_f16(o0, o1);
    *(unsigned*)&out_hi[o+2] = pack_f16(o2, o3);
}

// ---------------------------------------------------------------------------
// fp16 MMA GEMM: C = Ah[M,K] @ Bh^T[N,K] + bias (+R | gelu)
// CTA 128x128xBK16, 8 warps (2x4), warp tile 64x32, m16n8k16 mma.
// 3-stage cp.async pipeline (2 loads in flight); loop body unchanged from R11.
// EPI: 1 bias+R->f32 | 2 bias+gelu->fp16 | 3 bias->fp16
// ---------------------------------------------------------------------------
template<int EPI>
__global__ __launch_bounds__(256) void mma_gemm(
    const __half* __restrict__ Ah, const __half* __restrict__ Bh,
    const float* __restrict__ bias, const float* __restrict__ R,
    float* __restrict__ C, __half* __restrict__ Chi, int M, int N, int K)
{
    __shared__ __align__(16) __half smem[3][2][128 * LDS_K];   // 36,864 B

    const int tid = threadIdx.x;
    const int bm = blockIdx.y * 128;
    const int bn = blockIdx.x * 128;

    const int lrow  = tid >> 1;
    const int lhalf = tid & 1;
    const __half* src0 = Ah + (size_t)(bm + lrow) * K + lhalf * 8;
    const __half* src2 = Bh + (size_t)(bn + lrow) * K + lhalf * 8;
    const int sdst = lrow * LDS_K + lhalf * 8;

    const int warp  = tid >> 5;
    const int lane  = tid & 31;
    const int warpm = warp >> 2;
    const int warpn = warp & 3;
    const int g = lane >> 2;
    const int c = lane & 3;

    float acc[4][4][4];
    #pragma unroll
    for (int i = 0; i < 4; i++)
        #pragma unroll
        for (int j = 0; j < 4; j++)
            #pragma unroll
            for (int r = 0; r < 4; r++) acc[i][j][r] = 0.0f;

    const int nk = K >> 4;   // >= 2 always (K is 1024 or 4096)

    // prologue: stages 0 and 1
    cp16(&smem[0][0][sdst], src0);
    cp16(&smem[0][1][sdst], src2);
    asm volatile("cp.async.commit_group;\n" ::);
    cp16(&smem[1][0][sdst], src0 + 16);
    cp16(&smem[1][1][sdst], src2 + 16);
    asm volatile("cp.async.commit_group;\n" ::);

    int st = 0;   // stage index of tile t (mod 3)
    for (int t = 0; t < nk; t++) {
        // ensure stage t's group is complete
        if (t + 1 < nk) {
            asm volatile("cp.async.wait_group 1;\n" ::);
        } else {
            asm volatile("cp.async.wait_group 0;\n" ::);
        }
        __syncthreads();

        // prefetch stage t+2 (reuses buffer of tile t-1; safe after barrier)
        if (t + 2 < nk) {
            int ko = (t + 2) << 4;
            int sn = (st + 2 >= 3) ? st - 1 : st + 2;
            cp16(&smem[sn][0][sdst], src0 + ko);
            cp16(&smem[sn][1][sdst], src2 + ko);
            asm volatile("cp.async.commit_group;\n" ::);
        }

        const __half* sAh = smem[st][0];
        const __half* sBh = smem[st][1];

        unsigned ah[4][4], bh[4][2];
        const int abase = (warpm * 64 + g) * LDS_K + c * 2;
        const int bbase = (warpn * 32 + g) * LDS_K + c * 2;

        #pragma unroll
        for (int mi = 0; mi < 4; mi++) {
            int o = abase + mi * 16 * LDS_K;
            ah[mi][0] = *(const unsigned*)(sAh + o);
            ah[mi][1] = *(const unsigned*)(sAh + o + 8 * LDS_K);
            ah[mi][2] = *(const unsigned*)(sAh + o + 8);
            ah[mi][3] = *(const unsigned*)(sAh + o + 8 * LDS_K + 8);
        }
        #pragma unroll
        for (int ni = 0; ni < 4; ni++) {
            int o = bbase + ni * 8 * LDS_K;
            bh[ni][0] = *(const unsigned*)(sBh + o);
            bh[ni][1] = *(const unsigned*)(sBh + o + 8);
        }
        #pragma unroll
        for (int mi = 0; mi < 4; mi++)
            #pragma unroll
            for (int ni = 0; ni < 4; ni++)
                mma_f16(acc[mi][ni], ah[mi], bh[ni]);

        st = (st + 1 >= 3) ? 0 : st + 1;
    }

    #pragma unroll
    for (int mi = 0; mi < 4; mi++) {
        int r0 = bm + warpm * 64 + mi * 16 + g;
        #pragma unroll
        for (int ni = 0; ni < 4; ni++) {
            int col = bn + warpn * 32 + ni * 8 + c * 2;
            float2 bia = *(const float2*)&bias[col];
            float v0 = acc[mi][ni][0] + bia.x;
            float v1 = acc[mi][ni][1] + bia.y;
            float v2 = acc[mi][ni][2] + bia.x;
            float v3 = acc[mi][ni][3] + bia.y;
            size_t o0 = (size_t)r0 * N + col;
            size_t o1 = (size_t)(r0 + 8) * N + col;
            if (EPI == 1) {
                float2 ra = *(const float2*)&R[o0];
                float2 rb = *(const float2*)&R[o1];
                v0 += ra.x; v1 += ra.y; v2 += rb.x; v3 += rb.y;
                *(float2*)&C[o0] = make_float2(v0, v1);
                *(float2*)&C[o1] = make_float2(v2, v3);
            } else {
                if (EPI == 2) {
                    v0 = gelu_exact(v0); v1 = gelu_exact(v1);
                    v2 = gelu_exact(v2); v3 = gelu_exact(v3);
                }
                *(unsigned*)&Chi[o0] = pack_f16(v0, v1);
                *(unsigned*)&Chi[o1] = pack_f16(v2, v3);
            }
        }
    }
}

// ---------------------------------------------------------------------------
// fp16 flash attention, single term (R11 unchanged). Fused QKV input.
// ---------------------------------------------------------------------------
#define ATT_QH   0
#define ATT_ST   8192
#define ATT_TILE 8192
#define ATT_FM   (ATT_ST + 2*16384)      // 40960
#define ATT_SMEM (ATT_FM + 2*64*4)       // 41472
#define OFF_K    DMODEL
#define OFF_V    (2*DMODEL)

__device__ __forceinline__ unsigned swz(unsigned base, int row, int cc) {
    return base + (unsigned)((row << 7) + (((cc ^ row) & 7) << 4));
}

__global__ __launch_bounds__(128) void attn_mma(
    const __half* __restrict__ QKVh, const int* __restrict__ mask,
    __half* __restrict__ Ohi)
{
    extern __shared__ __align__(16) char sm[];
    const unsigned smb = (unsigned)__cvta_generic_to_shared(sm);
    float* fmask = (float*)(sm + ATT_FM);

    const int b  = blockIdx.z;
    const int h  = blockIdx.y;
    const int qt = blockIdx.x;
    const int tid  = threadIdx.x;
    const int warp = tid >> 5;
    const int lane = tid & 31;
    const int li  = lane & 7;
    const int grp = lane >> 3;
    const int g = lane >> 2;
    const int c = lane & 3;

    const int qrow0 = qt * 64;
    const size_t rowQ = (size_t)(b * SEQ + qrow0);

    {
        #pragma unroll
        for (int i = 0; i < 4; i++) {
            int idx = tid + i * 128;
            int row = idx >> 3, cc = idx & 7;
            size_t gq = (rowQ + row) * QKVN + h * DK + cc * 8;
            cp16(sm + swz(ATT_QH, row, cc), QKVh + gq);
        }
        #pragma unroll
        for (int i = 0; i < 4; i++) {
            int idx = tid + i * 128;
            int row = idx >> 3, cc = idx & 7;
            size_t gr = (size_t)(b * SEQ + row) * QKVN + h * DK + cc * 8;
            cp16(sm + swz(ATT_ST, row, cc), QKVh + gr + OFF_K);
            cp16(sm + swz(ATT_ST + ATT_TILE, row, cc), QKVh + gr + OFF_V);
        }
        if (tid < 64) fmask[tid] = (mask[b * SEQ + tid] != 0) ? 0.0f : -1e30f;
        asm volatile("cp.async.commit_group;\n" ::);
    }

    float oacc[8][4];
    #pragma unroll
    for (int nt = 0; nt < 8; nt++)
        #pragma unroll
        for (int r = 0; r < 4; r++) oacc[nt][r] = 0.0f;
    float m0 = -1e30f, m1 = -1e30f, l0 = 0.0f, l1 = 0.0f;
    unsigned qfh[4][4];

    const int NT = SEQ / 64;
    for (int kt = 0; kt < NT; kt++) {
        asm volatile("cp.async.wait_group 0;\n" ::);
        __syncthreads();

        if (kt == 0) {
            int qrow = warp * 16 + ((grp & 1) << 3) + li;
            #pragma unroll
            for (int q = 0; q < 4; q++) {
                int cc = 2 * q + (grp >> 1);
                ldsm4(qfh[q][0], qfh[q][1], qfh[q][2], qfh[q][3], smb + swz(ATT_QH, qrow, cc));
            }
        }

        if (kt + 1 < NT) {
            int s = (kt + 1) & 1;
            int kb = (kt + 1) * 64;
            #pragma unroll
            for (int i = 0; i < 4; i++) {
                int idx = tid + i * 128;
                int row = idx >> 3, cc = idx & 7;
                size_t gr = (size_t)(b * SEQ + kb + row) * QKVN + h * DK + cc * 8;
                cp16(sm + swz(ATT_ST + s*16384, row, cc), QKVh + gr + OFF_K);
                cp16(sm + swz(ATT_ST + s*16384 + ATT_TILE, row, cc), QKVh + gr + OFF_V);
            }
            if (tid < 64) fmask[s * 64 + tid] = (mask[b * SEQ + kb + tid] != 0) ? 0.0f : -1e30f;
            asm volatile("cp.async.commit_group;\n" ::);
        }

        const int s = kt & 1;
        const unsigned KHb = ATT_ST + s*16384;
        const unsigned VHb = KHb + ATT_TILE;
        const float* fm = fmask + s * 64;

        float sacc[8][4];
        #pragma unroll
        for (int nt = 0; nt < 8; nt++)
            #pragma unroll
            for (int r = 0; r < 4; r++) sacc[nt][r] = 0.0f;

        {
            const int krow = ((grp >> 1) << 3) + li;
            const int kccb = grp & 1;
            #pragma unroll
            for (int q = 0; q < 4; q++) {
                unsigned kb2[8][2];
                #pragma unroll
                for (int p = 0; p < 4; p++)
                    ldsm4(kb2[2*p][0], kb2[2*p][1], kb2[2*p+1][0], kb2[2*p+1][1],
                          smb + swz(KHb, 16*p + krow, 2*q + kccb));
                #pragma unroll
                for (int nt = 0; nt < 8; nt++) mma_f16(sacc[nt], qfh[q], kb2[nt]);
            }
        }

        float mx0 = -1e30f, mx1 = -1e30f;
        #pragma unroll
        for (int nt = 0; nt < 8; nt++) {
            float f0 = fm[nt*8 + 2*c];
            float f1 = fm[nt*8 + 2*c + 1];
            sacc[nt][0] = fmaf(sacc[nt][0], 0.125f, f0);
            sacc[nt][1] = fmaf(sacc[nt][1], 0.125f, f1);
            sacc[nt][2] = fmaf(sacc[nt][2], 0.125f, f0);
            sacc[nt][3] = fmaf(sacc[nt][3], 0.125f, f1);
            mx0 = fmaxf(mx0, fmaxf(sacc[nt][0], sacc[nt][1]));
            mx1 = fmaxf(mx1, fmaxf(sacc[nt][2], sacc[nt][3]));
        }
        mx0 = fmaxf(mx0, __shfl_xor_sync(0xffffffff, mx0, 1));
        mx0 = fmaxf(mx0, __shfl_xor_sync(0xffffffff, mx0, 2));
        mx1 = fmaxf(mx1, __shfl_xor_sync(0xffffffff, mx1, 1));
        mx1 = fmaxf(mx1, __shfl_xor_sync(0xffffffff, mx1, 2));

        float nm0 = fmaxf(m0, mx0), nm1 = fmaxf(m1, mx1);
        float sc0 = fexp(m0 - nm0), sc1 = fexp(m1 - nm1);
        m0 = nm0; m1 = nm1;
        l0 *= sc0; l1 *= sc1;
        #pragma unroll
        for (int nt = 0; nt < 8; nt++) {
            oacc[nt][0] *= sc0; oacc[nt][1] *= sc0;
            oacc[nt][2] *= sc1; oacc[nt][3] *= sc1;
        }

        float ls0 = 0.0f, ls1 = 0.0f;
        #pragma unroll
        for (int nt = 0; nt < 8; nt++) {
            float p0 = fexp(sacc[nt][0] - nm0);
            float p1 = fexp(sacc[nt][1] - nm0);
            float p2 = fexp(sacc[nt][2] - nm1);
            float p3 = fexp(sacc[nt][3] - nm1);
            sacc[nt][0] = p0; sacc[nt][1] = p1; sacc[nt][2] = p2; sacc[nt][3] = p3;
            ls0 += p0 + p1; ls1 += p2 + p3;
        }
        ls0 += __shfl_xor_sync(0xffffffff, ls0, 1);
        ls0 += __shfl_xor_sync(0xffffffff, ls0, 2);
        ls1 += __shfl_xor_sync(0xffffffff, ls1, 1);
        ls1 += __shfl_xor_sync(0xffffffff, ls1, 2);
        l0 += ls0; l1 += ls1;

        unsigned pfh[4][4];
        #pragma unroll
        for (int j = 0; j < 4; j++) {
            pfh[j][0] = pack_f16(sacc[2*j][0],   sacc[2*j][1]);
            pfh[j][1] = pack_f16(sacc[2*j][2],   sacc[2*j][3]);
            pfh[j][2] = pack_f16(sacc[2*j+1][0], sacc[2*j+1][1]);
            pfh[j][3] = pack_f16(sacc[2*j+1][2], sacc[2*j+1][3]);
        }

        {
            const int vrow = ((grp & 1) << 3) + li;
            const int vccb = grp >> 1;
            #pragma unroll
            for (int j = 0; j < 4; j++) {
                unsigned vb2[8][2];
                #pragma unroll
                for (int d = 0; d < 8; d += 2)
                    ldsm4t(vb2[d][0], vb2[d][1], vb2[d+1][0], vb2[d+1][1],
                           smb + swz(VHb, 16*j + vrow, d + vccb));
                #pragma unroll
                for (int nt = 0; nt < 8; nt++) mma_f16(oacc[nt], pfh[j], vb2[nt]);
            }
        }
    }

    float inv0 = 1.0f / l0, inv1 = 1.0f / l1;
    int r0 = qrow0 + warp * 16 + g;
    int r1 = r0 + 8;
    size_t base0 = (size_t)(b * SEQ + r0) * DMODEL + h * DK;
    size_t base1 = (size_t)(b * SEQ + r1) * DMODEL + h * DK;
    #pragma unroll
    for (int nt = 0; nt < 8; nt++) {
        int col = nt * 8 + 2 * c;
        *(unsigned*)&Ohi[base0 + col] = pack_f16(oacc[nt][0] * inv0, oacc[nt][1] * inv0);
        *(unsigned*)&Ohi[base1 + col] = pack_f16(oacc[nt][2] * inv1, oacc[nt][3] * inv1);
    }
}

// ---------------------------------------------------------------------------
// Host launch
// ---------------------------------------------------------------------------
extern "C" void kernel_launch(void* const* d_in, const int* in_sizes, int n_in,
                              void* d_out, int out_size)
{
    const float* x     = (const float*)d_in[0];
    const int*   mask  = (const int*)  d_in[1];
    const float* Wq    = (const float*)d_in[2];
    const float* bq    = (const float*)d_in[3];
    const float* Wk    = (const float*)d_in[4];
    const float* bk    = (const float*)d_in[5];
    const float* Wv    = (const float*)d_in[6];
    const float* bv    = (const float*)d_in[7];
    const float* Wo    = (const float*)d_in[8];
    const float* bo    = (const float*)d_in[9];
    const float* W1    = (const float*)d_in[10];
    const float* b1    = (const float*)d_in[11];
    const float* W2    = (const float*)d_in[12];
    const float* b2    = (const float*)d_in[13];
    const float* ln1_g = (const float*)d_in[14];
    const float* ln1_b = (const float*)d_in[15];
    const float* ln2_g = (const float*)d_in[16];
    const float* ln2_b = (const float*)d_in[17];
    float* out = (float*)d_out;

    float *x1, *bqkv;
    __half *hh, *qkvh, *ctxh, *h2h, *ffnh;
    __half *wqkvh, *woh, *w1h, *w2h;
    cudaGetSymbolAddress((void**)&x1,   g_x1);
    cudaGetSymbolAddress((void**)&bqkv, g_bqkv);
    cudaGetSymbolAddress((void**)&hh,   g_hh);
    cudaGetSymbolAddress((void**)&qkvh, g_qkvh);
    cudaGetSymbolAddress((void**)&ctxh, g_ctxh);
    cudaGetSymbolAddress((void**)&h2h,  g_h2h);
    cudaGetSymbolAddress((void**)&ffnh, g_ffnh);
    cudaGetSymbolAddress((void**)&wqkvh, g_wqkvh);
    cudaGetSymbolAddress((void**)&woh,  g_woh);
    cudaGetSymbolAddress((void**)&w1h,  g_w1h);
    cudaGetSymbolAddress((void**)&w2h,  g_w2h);

    cudaFuncSetAttribute(attn_mma, cudaFuncAttributeMaxDynamicSharedMemorySize, ATT_SMEM);

    dim3 gW(DMODEL/32, DMODEL/32);

    bias_concat_kernel<<<QKVN/256, 256>>>(bq, bk, bv, bqkv);
    wsplit_kernel<<<gW, 256>>>(Wq, wqkvh,                   DMODEL, DMODEL);
    wsplit_kernel<<<gW, 256>>>(Wk, wqkvh + DMODEL*DMODEL,   DMODEL, DMODEL);
    wsplit_kernel<<<gW, 256>>>(Wv, wqkvh + 2*DMODEL*DMODEL, DMODEL, DMODEL);
    ln_kernel<<<MROWS, 256>>>(x, ln1_g, ln1_b, hh);

    // fused QKV projection
    dim3 gQKV(QKVN/128, MROWS/128);
    mma_gemm<3><<<gQKV, 256>>>(hh, wqkvh, bqkv, nullptr, nullptr, qkvh, MROWS, QKVN, DMODEL);

    wsplit_kernel<<<gW, 256>>>(Wo, woh, DMODEL, DMODEL);
    dim3 gW1(DFF/32, DMODEL/32);
    wsplit_kernel<<<gW1, 256>>>(W1, w1h, DMODEL, DFF);
    dim3 gW2(DMODEL/32, DFF/32);
    wsplit_kernel<<<gW2, 256>>>(W2, w2h, DFF, DMODEL);

    // attention -> ctx fp16
    dim3 gA(SEQ/64, NHEADS, BATCH);
    attn_mma<<<gA, 128, ATT_SMEM>>>(qkvh, mask, ctxh);

    // output projection + residual -> x1 (fp32)
    dim3 gP(DMODEL/128, MROWS/128);
    mma_gemm<1><<<gP, 256>>>(ctxh, woh, bo, x, x1, nullptr, MROWS, DMODEL, DMODEL);

    // LN2 -> fp16
    ln_kernel<<<MROWS, 256>>>(x1, ln2_g, ln2_b, h2h);

    // FFN up + GELU -> fp16
    dim3 gF1(DFF/128, MROWS/128);
    mma_gemm<2><<<gF1, 256>>>(h2h, w1h, b1, nullptr, nullptr, ffnh, MROWS, DFF, DMODEL);

    // FFN down + residual -> out (fp32)
    dim3 gF2(DMODEL/128, MROWS/128);
    mma_gemm<1><<<gF2, 256>>>(ffnh, w2h, b2, x1, out, nullptr, MROWS, DMODEL, DFF);
}